// round 2
// baseline (speedup 1.0000x reference)
#include <cuda_runtime.h>

// ----------------------------------------------------------------------------
// Problem constants
// ----------------------------------------------------------------------------
constexpr int B_  = 8;
constexpr int N_  = 1024;
constexpr int D_  = 256;
constexpr int H_  = 8;
constexpr int DK_ = 32;
constexpr int FF_ = 1024;
constexpr int L_  = 4;
constexpr int ROWS = B_ * N_;          // 8192 token rows

// ----------------------------------------------------------------------------
// Scratch (device globals: no allocation allowed)
// ----------------------------------------------------------------------------
__device__ float g_Q  [ROWS * D_];
__device__ float g_K  [ROWS * D_];
__device__ float g_V  [ROWS * D_];
__device__ float g_ATT[ROWS * D_];
__device__ float g_X  [ROWS * D_];
__device__ float g_Hb [ROWS * FF_];
__device__ float g_Fb [ROWS * D_];

// ----------------------------------------------------------------------------
// Classic SGEMM: C[M,N] = A[M,K] @ B[K,N] (+bias) (+ReLU)
// BM=BN=128, BK=8, 256 threads, 8x8 per-thread microtile, float4 I/O.
// All dims here are multiples of the tile sizes (M=8192, N in {256,1024},
// K in {256,1024}) so no edge handling is needed.
// ----------------------------------------------------------------------------
template <bool BIAS, bool RELU>
__global__ __launch_bounds__(256, 2)
void sgemm_kernel(const float* __restrict__ A,
                  const float* __restrict__ Bm,
                  const float* __restrict__ bias,
                  float* __restrict__ C,
                  int M, int Nn, int Kk)
{
    __shared__ float As[8][128];
    __shared__ float Bs[8][128];

    const int tid = threadIdx.x;
    const int tr  = tid / 16;          // 0..15 (row group)
    const int tc  = tid % 16;          // 0..15 (col group)

    const int rowBase = blockIdx.y * 128;
    const int colBase = blockIdx.x * 128;

    // A tile load: each thread one float4 (row = tid/2, 4 cols)
    const int aRow = tid >> 1;         // 0..127
    const int aCol = (tid & 1) * 4;    // 0 or 4
    // B tile load: each thread one float4 (row = tid/32, 4 cols)
    const int bRow = tid >> 5;         // 0..7
    const int bCol = (tid & 31) * 4;   // 0..124

    float acc[8][8];
#pragma unroll
    for (int i = 0; i < 8; i++)
#pragma unroll
        for (int j = 0; j < 8; j++) acc[i][j] = 0.0f;

    for (int k0 = 0; k0 < Kk; k0 += 8) {
        float4 av = *reinterpret_cast<const float4*>(
            &A[(size_t)(rowBase + aRow) * Kk + k0 + aCol]);
        As[aCol + 0][aRow] = av.x;
        As[aCol + 1][aRow] = av.y;
        As[aCol + 2][aRow] = av.z;
        As[aCol + 3][aRow] = av.w;

        float4 bv = *reinterpret_cast<const float4*>(
            &Bm[(size_t)(k0 + bRow) * Nn + colBase + bCol]);
        *reinterpret_cast<float4*>(&Bs[bRow][bCol]) = bv;

        __syncthreads();

#pragma unroll
        for (int k = 0; k < 8; k++) {
            float ra[8], rb[8];
#pragma unroll
            for (int i = 0; i < 4; i++) {
                float4 t = *reinterpret_cast<const float4*>(&As[k][tr * 8 + i * 4]);
                ra[i * 4 + 0] = t.x; ra[i * 4 + 1] = t.y;
                ra[i * 4 + 2] = t.z; ra[i * 4 + 3] = t.w;
            }
#pragma unroll
            for (int j = 0; j < 2; j++) {
                float4 t = *reinterpret_cast<const float4*>(&Bs[k][tc * 8 + j * 4]);
                rb[j * 4 + 0] = t.x; rb[j * 4 + 1] = t.y;
                rb[j * 4 + 2] = t.z; rb[j * 4 + 3] = t.w;
            }
#pragma unroll
            for (int i = 0; i < 8; i++)
#pragma unroll
                for (int j = 0; j < 8; j++)
                    acc[i][j] = fmaf(ra[i], rb[j], acc[i][j]);
        }
        __syncthreads();
    }

#pragma unroll
    for (int i = 0; i < 8; i++) {
        const int row = rowBase + tr * 8 + i;
#pragma unroll
        for (int j = 0; j < 8; j += 4) {
            const int col = colBase + tc * 8 + j;
            float4 v;
            v.x = acc[i][j + 0];
            v.y = acc[i][j + 1];
            v.z = acc[i][j + 2];
            v.w = acc[i][j + 3];
            if (BIAS) {
                float4 bb = *reinterpret_cast<const float4*>(&bias[col]);
                v.x += bb.x; v.y += bb.y; v.z += bb.z; v.w += bb.w;
            }
            if (RELU) {
                v.x = fmaxf(v.x, 0.0f); v.y = fmaxf(v.y, 0.0f);
                v.z = fmaxf(v.z, 0.0f); v.w = fmaxf(v.w, 0.0f);
            }
            *reinterpret_cast<float4*>(&C[(size_t)row * Nn + col]) = v;
        }
    }
}

// ----------------------------------------------------------------------------
// Flash attention with geometric bias.
// Grid: (B*H, N/128). Block: 128 threads, one query row per thread.
// scores = (q.k)/sqrt(DK) + alpha * <coord_q, coord_k>; online softmax; O=P@V.
// ----------------------------------------------------------------------------
__global__ __launch_bounds__(128, 4)
void attn_kernel(const float* __restrict__ Q,
                 const float* __restrict__ K,
                 const float* __restrict__ V,
                 const float* __restrict__ coords,
                 const float* __restrict__ alpha,
                 int layer,
                 float* __restrict__ Out)
{
    __shared__ float Ks[128 * 32];
    __shared__ float Vs[128 * 32];
    __shared__ float ckx[128], cky[128], ckz[128];

    const int bh = blockIdx.x;
    const int b  = bh / H_;
    const int h  = bh % H_;
    const int n  = blockIdx.y * 128 + threadIdx.x;

    const float scale  = 0.17677669529663687f;   // 1/sqrt(32)
    const float alphav = alpha[layer];

    // Load & pre-scale q row
    float q[32];
    {
        const float4* qg = reinterpret_cast<const float4*>(
            &Q[((size_t)b * N_ + n) * D_ + h * DK_]);
#pragma unroll
        for (int j = 0; j < 8; j++) {
            float4 t = qg[j];
            q[4 * j + 0] = t.x * scale;
            q[4 * j + 1] = t.y * scale;
            q[4 * j + 2] = t.z * scale;
            q[4 * j + 3] = t.w * scale;
        }
    }
    const float cq0 = coords[((size_t)b * N_ + n) * 3 + 0];
    const float cq1 = coords[((size_t)b * N_ + n) * 3 + 1];
    const float cq2 = coords[((size_t)b * N_ + n) * 3 + 2];

    float o[32];
#pragma unroll
    for (int j = 0; j < 32; j++) o[j] = 0.0f;
    float mrun = -1e30f;
    float lrun = 0.0f;

    for (int kt = 0; kt < N_; kt += 128) {
        // cooperative tile load: thread m loads K/V row m
        const int m = threadIdx.x;
        {
            const float4* kg = reinterpret_cast<const float4*>(
                &K[((size_t)b * N_ + kt + m) * D_ + h * DK_]);
            const float4* vg = reinterpret_cast<const float4*>(
                &V[((size_t)b * N_ + kt + m) * D_ + h * DK_]);
            float4* ks = reinterpret_cast<float4*>(&Ks[m * 32]);
            float4* vs = reinterpret_cast<float4*>(&Vs[m * 32]);
#pragma unroll
            for (int j = 0; j < 8; j++) { ks[j] = kg[j]; vs[j] = vg[j]; }
            ckx[m] = coords[((size_t)b * N_ + kt + m) * 3 + 0];
            cky[m] = coords[((size_t)b * N_ + kt + m) * 3 + 1];
            ckz[m] = coords[((size_t)b * N_ + kt + m) * 3 + 2];
        }
        __syncthreads();

        for (int mm = 0; mm < 128; mm++) {
            const float4* kr = reinterpret_cast<const float4*>(&Ks[mm * 32]);
            float s = alphav * (cq0 * ckx[mm] + cq1 * cky[mm] + cq2 * ckz[mm]);
#pragma unroll
            for (int j = 0; j < 8; j++) {
                float4 kk = kr[j];
                s = fmaf(q[4 * j + 0], kk.x, s);
                s = fmaf(q[4 * j + 1], kk.y, s);
                s = fmaf(q[4 * j + 2], kk.z, s);
                s = fmaf(q[4 * j + 3], kk.w, s);
            }
            const float mnew = fmaxf(mrun, s);
            const float c = __expf(mrun - mnew);
            const float p = __expf(s - mnew);
            lrun = lrun * c + p;
            const float4* vr = reinterpret_cast<const float4*>(&Vs[mm * 32]);
#pragma unroll
            for (int j = 0; j < 8; j++) {
                float4 vv = vr[j];
                o[4 * j + 0] = fmaf(p, vv.x, o[4 * j + 0] * c);
                o[4 * j + 1] = fmaf(p, vv.y, o[4 * j + 1] * c);
                o[4 * j + 2] = fmaf(p, vv.z, o[4 * j + 2] * c);
                o[4 * j + 3] = fmaf(p, vv.w, o[4 * j + 3] * c);
            }
            mrun = mnew;
        }
        __syncthreads();
    }

    const float inv = 1.0f / lrun;
    float4* og = reinterpret_cast<float4*>(
        &Out[((size_t)b * N_ + n) * D_ + h * DK_]);
#pragma unroll
    for (int j = 0; j < 8; j++) {
        og[j] = make_float4(o[4 * j + 0] * inv, o[4 * j + 1] * inv,
                            o[4 * j + 2] * inv, o[4 * j + 3] * inv);
    }
}

// ----------------------------------------------------------------------------
// Fused residual add + LayerNorm. Warp per row (D=256 -> 8 floats per lane).
// Block: 256 threads = 8 rows. out = LN(x + delta) * g + b.
// ----------------------------------------------------------------------------
__global__ __launch_bounds__(256, 6)
void add_ln_kernel(const float* __restrict__ x,
                   const float* __restrict__ delta,
                   const float* __restrict__ g,
                   const float* __restrict__ be,
                   float* __restrict__ out)
{
    const int warp = threadIdx.x >> 5;
    const int lane = threadIdx.x & 31;
    const int row  = blockIdx.x * 8 + warp;
    const int col0 = lane * 8;

    const float4* xr = reinterpret_cast<const float4*>(&x[(size_t)row * D_ + col0]);
    const float4* dr = reinterpret_cast<const float4*>(&delta[(size_t)row * D_ + col0]);

    float r[8];
    {
        float4 a0 = xr[0], a1 = xr[1], b0 = dr[0], b1 = dr[1];
        r[0] = a0.x + b0.x; r[1] = a0.y + b0.y; r[2] = a0.z + b0.z; r[3] = a0.w + b0.w;
        r[4] = a1.x + b1.x; r[5] = a1.y + b1.y; r[6] = a1.z + b1.z; r[7] = a1.w + b1.w;
    }

    float s = 0.0f;
#pragma unroll
    for (int j = 0; j < 8; j++) s += r[j];
#pragma unroll
    for (int off = 16; off > 0; off >>= 1) s += __shfl_xor_sync(0xffffffffu, s, off);
    const float mean = s * (1.0f / 256.0f);

    float v = 0.0f;
#pragma unroll
    for (int j = 0; j < 8; j++) { float t = r[j] - mean; v = fmaf(t, t, v); }
#pragma unroll
    for (int off = 16; off > 0; off >>= 1) v += __shfl_xor_sync(0xffffffffu, v, off);
    const float rs = rsqrtf(v * (1.0f / 256.0f) + 1e-5f);

    const float4* gg = reinterpret_cast<const float4*>(&g[col0]);
    const float4* bb = reinterpret_cast<const float4*>(&be[col0]);
    float4 g0 = gg[0], g1 = gg[1], e0 = bb[0], e1 = bb[1];

    float4 o0, o1;
    o0.x = (r[0] - mean) * rs * g0.x + e0.x;
    o0.y = (r[1] - mean) * rs * g0.y + e0.y;
    o0.z = (r[2] - mean) * rs * g0.z + e0.z;
    o0.w = (r[3] - mean) * rs * g0.w + e0.w;
    o1.x = (r[4] - mean) * rs * g1.x + e1.x;
    o1.y = (r[5] - mean) * rs * g1.y + e1.y;
    o1.z = (r[6] - mean) * rs * g1.z + e1.z;
    o1.w = (r[7] - mean) * rs * g1.w + e1.w;

    float4* orow = reinterpret_cast<float4*>(&out[(size_t)row * D_ + col0]);
    orow[0] = o0;
    orow[1] = o1;
}

// ----------------------------------------------------------------------------
// Host driver
// ----------------------------------------------------------------------------
extern "C" void kernel_launch(void* const* d_in, const int* in_sizes, int n_in,
                              void* d_out, int out_size)
{
    const float* x      = (const float*)d_in[0];
    const float* coords = (const float*)d_in[1];
    const float* Wq     = (const float*)d_in[2];
    const float* bq     = (const float*)d_in[3];
    const float* Wk     = (const float*)d_in[4];
    const float* bk     = (const float*)d_in[5];
    const float* Wv     = (const float*)d_in[6];
    const float* bv     = (const float*)d_in[7];
    const float* alpha  = (const float*)d_in[8];
    const float* W1     = (const float*)d_in[9];
    const float* b1     = (const float*)d_in[10];
    const float* W2     = (const float*)d_in[11];
    const float* b2     = (const float*)d_in[12];
    const float* g1     = (const float*)d_in[13];
    const float* be1    = (const float*)d_in[14];
    const float* g2     = (const float*)d_in[15];
    const float* be2    = (const float*)d_in[16];
    float* out = (float*)d_out;

    float *Qp, *Kp, *Vp, *Ap, *Xp, *Hp, *Fp;
    cudaGetSymbolAddress((void**)&Qp, g_Q);
    cudaGetSymbolAddress((void**)&Kp, g_K);
    cudaGetSymbolAddress((void**)&Vp, g_V);
    cudaGetSymbolAddress((void**)&Ap, g_ATT);
    cudaGetSymbolAddress((void**)&Xp, g_X);
    cudaGetSymbolAddress((void**)&Hp, g_Hb);
    cudaGetSymbolAddress((void**)&Fp, g_Fb);

    const dim3 gQKV(D_ / 128, ROWS / 128);   // (2, 64)
    const dim3 gFF1(FF_ / 128, ROWS / 128);  // (8, 64)
    const dim3 gFF2(D_ / 128, ROWS / 128);   // (2, 64)
    const dim3 gAttn(B_ * H_, N_ / 128);     // (64, 8)

    const float* cur = x;
    for (int i = 0; i < L_; i++) {
        sgemm_kernel<true, false><<<gQKV, 256>>>(cur, Wq + (size_t)i * D_ * D_,
                                                 bq + i * D_, Qp, ROWS, D_, D_);
        sgemm_kernel<true, false><<<gQKV, 256>>>(cur, Wk + (size_t)i * D_ * D_,
                                                 bk + i * D_, Kp, ROWS, D_, D_);
        sgemm_kernel<true, false><<<gQKV, 256>>>(cur, Wv + (size_t)i * D_ * D_,
                                                 bv + i * D_, Vp, ROWS, D_, D_);

        attn_kernel<<<gAttn, 128>>>(Qp, Kp, Vp, coords, alpha, i, Ap);

        add_ln_kernel<<<ROWS / 8, 256>>>(cur, Ap, g1 + i * D_, be1 + i * D_, Xp);

        sgemm_kernel<true, true ><<<gFF1, 256>>>(Xp, W1 + (size_t)i * D_ * FF_,
                                                 b1 + i * FF_, Hp, ROWS, FF_, D_);
        sgemm_kernel<true, false><<<gFF2, 256>>>(Hp, W2 + (size_t)i * FF_ * D_,
                                                 b2 + i * D_, Fp, ROWS, D_, FF_);

        float* xo = (i == L_ - 1) ? out : Xp;
        add_ln_kernel<<<ROWS / 8, 256>>>(Xp, Fp, g2 + i * D_, be2 + i * D_, xo);

        cur = Xp;
    }
}

// round 4
// speedup vs baseline: 1.8194x; 1.8194x over previous
#include <cuda_runtime.h>
#include <cstdint>

// ----------------------------------------------------------------------------
// Problem constants
// ----------------------------------------------------------------------------
constexpr int B_  = 8;
constexpr int N_  = 1024;
constexpr int D_  = 256;
constexpr int H_  = 8;
constexpr int DK_ = 32;
constexpr int FF_ = 1024;
constexpr int L_  = 4;
constexpr int ROWS = B_ * N_;          // 8192 token rows

// ----------------------------------------------------------------------------
// Scratch (device globals: no allocation allowed)
// ----------------------------------------------------------------------------
__device__ float g_Q  [ROWS * D_];
__device__ float g_K  [ROWS * D_];
__device__ float g_V  [ROWS * D_];
__device__ float g_ATT[ROWS * D_];
__device__ float g_X  [ROWS * D_];
__device__ float g_Hb [ROWS * FF_];
__device__ float g_Fb [ROWS * D_];

// ----------------------------------------------------------------------------
// Helpers
// ----------------------------------------------------------------------------
__device__ __forceinline__ uint32_t smem_u32(const void* p) {
    return (uint32_t)__cvta_generic_to_shared(p);
}
__device__ __forceinline__ void cp16(uint32_t s, const void* g) {
    asm volatile("cp.async.cg.shared.global [%0], [%1], 16;" :: "r"(s), "l"(g));
}
__device__ __forceinline__ void cp_commit() {
    asm volatile("cp.async.commit_group;" ::: "memory");
}
template <int NN>
__device__ __forceinline__ void cp_wait() {
    asm volatile("cp.async.wait_group %0;" :: "n"(NN) : "memory");
}
__device__ __forceinline__ void mma_tf32(float* c, const uint32_t* a, const uint32_t* b) {
    asm volatile(
        "mma.sync.aligned.m16n8k8.row.col.f32.tf32.tf32.f32 "
        "{%0,%1,%2,%3},{%4,%5,%6,%7},{%8,%9},{%0,%1,%2,%3};"
        : "+f"(c[0]), "+f"(c[1]), "+f"(c[2]), "+f"(c[3])
        : "r"(a[0]), "r"(a[1]), "r"(a[2]), "r"(a[3]), "r"(b[0]), "r"(b[1]));
}

// ----------------------------------------------------------------------------
// tf32 MMA GEMM: C[M,Nn] = A[M,Kk] @ Bw[Kk,Nn] (+bias)(+ReLU)
// CTA tile 128x128, BK=32, 8 warps (4x2), warp tile 32x64.
// Double-buffered cp.async pipeline. Smem: A XOR-swizzled, B padded stride 136.
// ----------------------------------------------------------------------------
constexpr int A_TILE_U32 = 128 * 32;           // 4096
constexpr int B_TILE_U32 = 32 * 136;           // 4352
constexpr int GEMM_SMEM  = 2 * (A_TILE_U32 + B_TILE_U32) * 4;  // 67584 bytes

template <bool RELU>
__device__ __forceinline__ void gemm_body(const float* __restrict__ A,
                                          const float* __restrict__ Bw,
                                          const float* __restrict__ bias,
                                          float* __restrict__ C,
                                          int Nn, int Kk)
{
    extern __shared__ uint32_t sm[];
    uint32_t* As = sm;                      // [2][4096]
    uint32_t* Bs = sm + 2 * A_TILE_U32;     // [2][4352]

    const int tid  = threadIdx.x;
    const int lane = tid & 31;
    const int warp = tid >> 5;
    const int gid  = lane >> 2;             // 0..7
    const int tig  = lane & 3;              // 0..3
    const int wm   = warp & 3;              // 4 row warps * 32 rows
    const int wn   = warp >> 2;             // 2 col warps * 64 cols

    const int rowBase = blockIdx.y * 128;
    const int colBase = blockIdx.x * 128;

    // staging coordinates (4 float4 each for A and B per BK tile)
    int aR[4], aS[4], bR[4], bS[4];
#pragma unroll
    for (int i = 0; i < 4; i++) {
        int idx = tid + i * 256;
        int r  = idx >> 3;
        int c4 = (idx & 7) << 2;
        aR[i] = r; aS[i] = r * 32 + (c4 ^ ((r & 7) << 2));
        int rb  = idx >> 5;
        int cb4 = (idx & 31) << 2;
        bR[i] = rb; bS[i] = rb * 136 + cb4;
    }
    int aC4[4], bC4[4];
#pragma unroll
    for (int i = 0; i < 4; i++) {
        int idx = tid + i * 256;
        aC4[i] = (idx & 7) << 2;
        bC4[i] = (idx & 31) << 2;
    }

    auto issue = [&](int t, int buf) {
        const int k0 = t * 32;
#pragma unroll
        for (int i = 0; i < 4; i++) {
            cp16(smem_u32(&As[buf * A_TILE_U32 + aS[i]]),
                 &A[(size_t)(rowBase + aR[i]) * Kk + k0 + aC4[i]]);
        }
#pragma unroll
        for (int i = 0; i < 4; i++) {
            cp16(smem_u32(&Bs[buf * B_TILE_U32 + bS[i]]),
                 &Bw[(size_t)(k0 + bR[i]) * Nn + colBase + bC4[i]]);
        }
        cp_commit();
    };

    float acc[2][8][4];
#pragma unroll
    for (int mt = 0; mt < 2; mt++)
#pragma unroll
        for (int nt = 0; nt < 8; nt++)
#pragma unroll
            for (int j = 0; j < 4; j++) acc[mt][nt][j] = 0.0f;

    const int T = Kk >> 5;
    issue(0, 0);
    issue(1, 1);

    for (int t = 0; t < T; t++) {
        if (t + 1 < T) cp_wait<1>(); else cp_wait<0>();
        __syncthreads();

        const int buf = t & 1;
        const uint32_t* Ab = &As[buf * A_TILE_U32];
        const uint32_t* Bb = &Bs[buf * B_TILE_U32];

#pragma unroll
        for (int kk = 0; kk < 32; kk += 8) {
            uint32_t a[2][4];
#pragma unroll
            for (int mt = 0; mt < 2; mt++) {
                const int m  = wm * 32 + mt * 16 + gid;
                const int sw = (m & 7) << 2;
                const int b0 = m * 32;
                const int b1 = b0 + 8 * 32;
                a[mt][0] = Ab[b0 + (kk ^ sw) + tig];
                a[mt][1] = Ab[b1 + (kk ^ sw) + tig];
                a[mt][2] = Ab[b0 + ((kk + 4) ^ sw) + tig];
                a[mt][3] = Ab[b1 + ((kk + 4) ^ sw) + tig];
            }
            uint32_t b[8][2];
#pragma unroll
            for (int nt = 0; nt < 8; nt++) {
                const int n = wn * 64 + nt * 8 + gid;
                b[nt][0] = Bb[(kk + tig) * 136 + n];
                b[nt][1] = Bb[(kk + tig + 4) * 136 + n];
            }
#pragma unroll
            for (int mt = 0; mt < 2; mt++)
#pragma unroll
                for (int nt = 0; nt < 8; nt++)
                    mma_tf32(acc[mt][nt], a[mt], b[nt]);
        }
        __syncthreads();
        if (t + 2 < T) issue(t + 2, buf);
    }

    // epilogue
#pragma unroll
    for (int mt = 0; mt < 2; mt++) {
        const int row0 = rowBase + wm * 32 + mt * 16 + gid;
        const int row1 = row0 + 8;
#pragma unroll
        for (int nt = 0; nt < 8; nt++) {
            const int col = colBase + wn * 64 + nt * 8 + 2 * tig;
            float2 bb = *reinterpret_cast<const float2*>(&bias[col]);
            float v0 = acc[mt][nt][0] + bb.x;
            float v1 = acc[mt][nt][1] + bb.y;
            float v2 = acc[mt][nt][2] + bb.x;
            float v3 = acc[mt][nt][3] + bb.y;
            if (RELU) {
                v0 = fmaxf(v0, 0.0f); v1 = fmaxf(v1, 0.0f);
                v2 = fmaxf(v2, 0.0f); v3 = fmaxf(v3, 0.0f);
            }
            *reinterpret_cast<float2*>(&C[(size_t)row0 * Nn + col]) = make_float2(v0, v1);
            *reinterpret_cast<float2*>(&C[(size_t)row1 * Nn + col]) = make_float2(v2, v3);
        }
    }
}

// Fused QKV: grid.z selects which projection this CTA computes.
__global__ __launch_bounds__(256, 2)
void qkv_kernel(const float* __restrict__ A,
                const float* __restrict__ Wq, const float* __restrict__ Wk,
                const float* __restrict__ Wv,
                const float* __restrict__ bq, const float* __restrict__ bk,
                const float* __restrict__ bv,
                float* __restrict__ Qo, float* __restrict__ Ko, float* __restrict__ Vo)
{
    const float* Bw; const float* bias; float* C;
    if (blockIdx.z == 0)      { Bw = Wq; bias = bq; C = Qo; }
    else if (blockIdx.z == 1) { Bw = Wk; bias = bk; C = Ko; }
    else                      { Bw = Wv; bias = bv; C = Vo; }
    gemm_body<false>(A, Bw, bias, C, D_, D_);
}

template <bool RELU>
__global__ __launch_bounds__(256, 2)
void ff_kernel(const float* __restrict__ A, const float* __restrict__ Bw,
               const float* __restrict__ bias, float* __restrict__ C,
               int Nn, int Kk)
{
    gemm_body<RELU>(A, Bw, bias, C, Nn, Kk);
}

// ----------------------------------------------------------------------------
// Flash attention with geometric bias, deferred max-rescale.
// Grid: (B*H, N/128). Block: 128 threads, one query row per thread.
// ----------------------------------------------------------------------------
__global__ __launch_bounds__(128, 4)
void attn_kernel(const float* __restrict__ Q,
                 const float* __restrict__ K,
                 const float* __restrict__ V,
                 const float* __restrict__ coords,
                 const float* __restrict__ alpha,
                 int layer,
                 float* __restrict__ Out)
{
    __shared__ float Ks[128 * 32];
    __shared__ float Vs[128 * 32];
    __shared__ float ckx[128], cky[128], ckz[128];

    const int bh = blockIdx.x;
    const int b  = bh / H_;
    const int h  = bh % H_;
    const int n  = blockIdx.y * 128 + threadIdx.x;

    const float scale  = 0.17677669529663687f;   // 1/sqrt(32)
    const float alphav = alpha[layer];

    float q[32];
    {
        const float4* qg = reinterpret_cast<const float4*>(
            &Q[((size_t)b * N_ + n) * D_ + h * DK_]);
#pragma unroll
        for (int j = 0; j < 8; j++) {
            float4 t = qg[j];
            q[4 * j + 0] = t.x * scale;
            q[4 * j + 1] = t.y * scale;
            q[4 * j + 2] = t.z * scale;
            q[4 * j + 3] = t.w * scale;
        }
    }
    const float acq0 = alphav * coords[((size_t)b * N_ + n) * 3 + 0];
    const float acq1 = alphav * coords[((size_t)b * N_ + n) * 3 + 1];
    const float acq2 = alphav * coords[((size_t)b * N_ + n) * 3 + 2];

    float o[32];
#pragma unroll
    for (int j = 0; j < 32; j++) o[j] = 0.0f;
    float mrun = -1e30f;
    float lrun = 0.0f;

    for (int kt = 0; kt < N_; kt += 128) {
        const int m = threadIdx.x;
        {
            const float4* kg = reinterpret_cast<const float4*>(
                &K[((size_t)b * N_ + kt + m) * D_ + h * DK_]);
            const float4* vg = reinterpret_cast<const float4*>(
                &V[((size_t)b * N_ + kt + m) * D_ + h * DK_]);
            float4* ks = reinterpret_cast<float4*>(&Ks[m * 32]);
            float4* vs = reinterpret_cast<float4*>(&Vs[m * 32]);
#pragma unroll
            for (int j = 0; j < 8; j++) { ks[j] = kg[j]; vs[j] = vg[j]; }
            ckx[m] = coords[((size_t)b * N_ + kt + m) * 3 + 0];
            cky[m] = coords[((size_t)b * N_ + kt + m) * 3 + 1];
            ckz[m] = coords[((size_t)b * N_ + kt + m) * 3 + 2];
        }
        __syncthreads();

        for (int mm = 0; mm < 128; mm++) {
            const float4* kr = reinterpret_cast<const float4*>(&Ks[mm * 32]);
            float s = acq0 * ckx[mm] + acq1 * cky[mm] + acq2 * ckz[mm];
#pragma unroll
            for (int j = 0; j < 8; j++) {
                float4 kk = kr[j];
                s = fmaf(q[4 * j + 0], kk.x, s);
                s = fmaf(q[4 * j + 1], kk.y, s);
                s = fmaf(q[4 * j + 2], kk.z, s);
                s = fmaf(q[4 * j + 3], kk.w, s);
            }
            const float4* vr = reinterpret_cast<const float4*>(&Vs[mm * 32]);
            if (s <= mrun) {
                // common path: no rescale
                const float p = __expf(s - mrun);
                lrun += p;
#pragma unroll
                for (int j = 0; j < 8; j++) {
                    float4 vv = vr[j];
                    o[4 * j + 0] = fmaf(p, vv.x, o[4 * j + 0]);
                    o[4 * j + 1] = fmaf(p, vv.y, o[4 * j + 1]);
                    o[4 * j + 2] = fmaf(p, vv.z, o[4 * j + 2]);
                    o[4 * j + 3] = fmaf(p, vv.w, o[4 * j + 3]);
                }
            } else {
                // new max: rescale once, p == 1
                const float c = __expf(mrun - s);
                mrun = s;
                lrun = fmaf(lrun, c, 1.0f);
#pragma unroll
                for (int j = 0; j < 8; j++) {
                    float4 vv = vr[j];
                    o[4 * j + 0] = fmaf(o[4 * j + 0], c, vv.x);
                    o[4 * j + 1] = fmaf(o[4 * j + 1], c, vv.y);
                    o[4 * j + 2] = fmaf(o[4 * j + 2], c, vv.z);
                    o[4 * j + 3] = fmaf(o[4 * j + 3], c, vv.w);
                }
            }
        }
        __syncthreads();
    }

    const float inv = 1.0f / lrun;
    float4* og = reinterpret_cast<float4*>(
        &Out[((size_t)b * N_ + n) * D_ + h * DK_]);
#pragma unroll
    for (int j = 0; j < 8; j++) {
        og[j] = make_float4(o[4 * j + 0] * inv, o[4 * j + 1] * inv,
                            o[4 * j + 2] * inv, o[4 * j + 3] * inv);
    }
}

// ----------------------------------------------------------------------------
// Fused residual add + LayerNorm. Warp per row.
// ----------------------------------------------------------------------------
__global__ __launch_bounds__(256, 6)
void add_ln_kernel(const float* __restrict__ x,
                   const float* __restrict__ delta,
                   const float* __restrict__ g,
                   const float* __restrict__ be,
                   float* __restrict__ out)
{
    const int warp = threadIdx.x >> 5;
    const int lane = threadIdx.x & 31;
    const int row  = blockIdx.x * 8 + warp;
    const int col0 = lane * 8;

    const float4* xr = reinterpret_cast<const float4*>(&x[(size_t)row * D_ + col0]);
    const float4* dr = reinterpret_cast<const float4*>(&delta[(size_t)row * D_ + col0]);

    float r[8];
    {
        float4 a0 = xr[0], a1 = xr[1], b0 = dr[0], b1 = dr[1];
        r[0] = a0.x + b0.x; r[1] = a0.y + b0.y; r[2] = a0.z + b0.z; r[3] = a0.w + b0.w;
        r[4] = a1.x + b1.x; r[5] = a1.y + b1.y; r[6] = a1.z + b1.z; r[7] = a1.w + b1.w;
    }

    float s = 0.0f;
#pragma unroll
    for (int j = 0; j < 8; j++) s += r[j];
#pragma unroll
    for (int off = 16; off > 0; off >>= 1) s += __shfl_xor_sync(0xffffffffu, s, off);
    const float mean = s * (1.0f / 256.0f);

    float v = 0.0f;
#pragma unroll
    for (int j = 0; j < 8; j++) { float t = r[j] - mean; v = fmaf(t, t, v); }
#pragma unroll
    for (int off = 16; off > 0; off >>= 1) v += __shfl_xor_sync(0xffffffffu, v, off);
    const float rs = rsqrtf(v * (1.0f / 256.0f) + 1e-5f);

    const float4* gg = reinterpret_cast<const float4*>(&g[col0]);
    const float4* bb = reinterpret_cast<const float4*>(&be[col0]);
    float4 g0 = gg[0], g1 = gg[1], e0 = bb[0], e1 = bb[1];

    float4 o0, o1;
    o0.x = (r[0] - mean) * rs * g0.x + e0.x;
    o0.y = (r[1] - mean) * rs * g0.y + e0.y;
    o0.z = (r[2] - mean) * rs * g0.z + e0.z;
    o0.w = (r[3] - mean) * rs * g0.w + e0.w;
    o1.x = (r[4] - mean) * rs * g1.x + e1.x;
    o1.y = (r[5] - mean) * rs * g1.y + e1.y;
    o1.z = (r[6] - mean) * rs * g1.z + e1.z;
    o1.w = (r[7] - mean) * rs * g1.w + e1.w;

    float4* orow = reinterpret_cast<float4*>(&out[(size_t)row * D_ + col0]);
    orow[0] = o0;
    orow[1] = o1;
}

// ----------------------------------------------------------------------------
// Host driver
// ----------------------------------------------------------------------------
extern "C" void kernel_launch(void* const* d_in, const int* in_sizes, int n_in,
                              void* d_out, int out_size)
{
    const float* x      = (const float*)d_in[0];
    const float* coords = (const float*)d_in[1];
    const float* Wq     = (const float*)d_in[2];
    const float* bq     = (const float*)d_in[3];
    const float* Wk     = (const float*)d_in[4];
    const float* bk     = (const float*)d_in[5];
    const float* Wv     = (const float*)d_in[6];
    const float* bv     = (const float*)d_in[7];
    const float* alpha  = (const float*)d_in[8];
    const float* W1     = (const float*)d_in[9];
    const float* b1     = (const float*)d_in[10];
    const float* W2     = (const float*)d_in[11];
    const float* b2     = (const float*)d_in[12];
    const float* g1     = (const float*)d_in[13];
    const float* be1    = (const float*)d_in[14];
    const float* g2     = (const float*)d_in[15];
    const float* be2    = (const float*)d_in[16];
    float* out = (float*)d_out;

    float *Qp, *Kp, *Vp, *Ap, *Xp, *Hp, *Fp;
    cudaGetSymbolAddress((void**)&Qp, g_Q);
    cudaGetSymbolAddress((void**)&Kp, g_K);
    cudaGetSymbolAddress((void**)&Vp, g_V);
    cudaGetSymbolAddress((void**)&Ap, g_ATT);
    cudaGetSymbolAddress((void**)&Xp, g_X);
    cudaGetSymbolAddress((void**)&Hp, g_Hb);
    cudaGetSymbolAddress((void**)&Fp, g_Fb);

    cudaFuncSetAttribute(qkv_kernel,
                         cudaFuncAttributeMaxDynamicSharedMemorySize, GEMM_SMEM);
    cudaFuncSetAttribute(ff_kernel<true>,
                         cudaFuncAttributeMaxDynamicSharedMemorySize, GEMM_SMEM);
    cudaFuncSetAttribute(ff_kernel<false>,
                         cudaFuncAttributeMaxDynamicSharedMemorySize, GEMM_SMEM);

    const dim3 gQKV(D_ / 128, ROWS / 128, 3);  // (2, 64, 3)
    const dim3 gFF1(FF_ / 128, ROWS / 128);    // (8, 64)
    const dim3 gFF2(D_ / 128, ROWS / 128);     // (2, 64)
    const dim3 gAttn(B_ * H_, N_ / 128);       // (64, 8)

    const float* cur = x;
    for (int i = 0; i < L_; i++) {
        qkv_kernel<<<gQKV, 256, GEMM_SMEM>>>(
            cur,
            Wq + (size_t)i * D_ * D_, Wk + (size_t)i * D_ * D_, Wv + (size_t)i * D_ * D_,
            bq + i * D_, bk + i * D_, bv + i * D_,
            Qp, Kp, Vp);

        attn_kernel<<<gAttn, 128>>>(Qp, Kp, Vp, coords, alpha, i, Ap);

        add_ln_kernel<<<ROWS / 8, 256>>>(cur, Ap, g1 + i * D_, be1 + i * D_, Xp);

        ff_kernel<true ><<<gFF1, 256, GEMM_SMEM>>>(Xp, W1 + (size_t)i * D_ * FF_,
                                                   b1 + i * FF_, Hp, FF_, D_);
        ff_kernel<false><<<gFF2, 256, GEMM_SMEM>>>(Hp, W2 + (size_t)i * FF_ * D_,
                                                   b2 + i * D_, Fp, D_, FF_);

        float* xo = (i == L_ - 1) ? out : Xp;
        add_ln_kernel<<<ROWS / 8, 256>>>(Xp, Fp, g2 + i * D_, be2 + i * D_, xo);

        cur = Xp;
    }
}

// round 8
// speedup vs baseline: 4.7660x; 2.6195x over previous
#include <cuda_runtime.h>
#include <cstdint>

// ----------------------------------------------------------------------------
// Problem constants
// ----------------------------------------------------------------------------
constexpr int B_  = 8;
constexpr int N_  = 1024;
constexpr int D_  = 256;
constexpr int H_  = 8;
constexpr int DK_ = 32;
constexpr int FF_ = 1024;
constexpr int L_  = 4;
constexpr int ROWS = B_ * N_;          // 8192 token rows

// ----------------------------------------------------------------------------
// Scratch (device globals: no allocation allowed)
// ----------------------------------------------------------------------------
__device__ float g_Q  [ROWS * D_];
__device__ float g_K  [ROWS * D_];
__device__ float g_V  [ROWS * D_];
__device__ float g_ATT[ROWS * D_];
__device__ float g_X  [ROWS * D_];
__device__ float g_Hb [ROWS * FF_];
__device__ float g_Fb [ROWS * D_];
// Attention staging buffers in mma-fragment-tiled layout.
// K' : per (bh, ktile): 40 kk x 128 keys -> 5120 floats
// V  : per (bh, ktile): 128 keys x 32 dk -> 4096 floats
__device__ __align__(16) float g_Kaug[64 * 8 * 5120];
__device__ __align__(16) float g_Vaug[64 * 8 * 4096];

// ----------------------------------------------------------------------------
// Helpers
// ----------------------------------------------------------------------------
__device__ __forceinline__ uint32_t smem_u32(const void* p) {
    return (uint32_t)__cvta_generic_to_shared(p);
}
__device__ __forceinline__ void cp16(uint32_t s, const void* g) {
    asm volatile("cp.async.cg.shared.global [%0], [%1], 16;" :: "r"(s), "l"(g));
}
__device__ __forceinline__ void cp_commit() {
    asm volatile("cp.async.commit_group;" ::: "memory");
}
template <int NN>
__device__ __forceinline__ void cp_wait() {
    asm volatile("cp.async.wait_group %0;" :: "n"(NN) : "memory");
}
__device__ __forceinline__ void mma_tf32(float* c, const uint32_t* a, const uint32_t* b) {
    asm volatile(
        "mma.sync.aligned.m16n8k8.row.col.f32.tf32.tf32.f32 "
        "{%0,%1,%2,%3},{%4,%5,%6,%7},{%8,%9},{%0,%1,%2,%3};"
        : "+f"(c[0]), "+f"(c[1]), "+f"(c[2]), "+f"(c[3])
        : "r"(a[0]), "r"(a[1]), "r"(a[2]), "r"(a[3]), "r"(b[0]), "r"(b[1]));
}

// ----------------------------------------------------------------------------
// tf32 MMA GEMM (unchanged from R3): C = A @ Bw (+bias)(+ReLU)
// ----------------------------------------------------------------------------
constexpr int A_TILE_U32 = 128 * 32;
constexpr int B_TILE_U32 = 32 * 136;
constexpr int GEMM_SMEM  = 2 * (A_TILE_U32 + B_TILE_U32) * 4;

template <bool RELU>
__device__ __forceinline__ void gemm_body(const float* __restrict__ A,
                                          const float* __restrict__ Bw,
                                          const float* __restrict__ bias,
                                          float* __restrict__ C,
                                          int Nn, int Kk)
{
    extern __shared__ uint32_t sm[];
    uint32_t* As = sm;
    uint32_t* Bs = sm + 2 * A_TILE_U32;

    const int tid  = threadIdx.x;
    const int lane = tid & 31;
    const int warp = tid >> 5;
    const int gid  = lane >> 2;
    const int tig  = lane & 3;
    const int wm   = warp & 3;
    const int wn   = warp >> 2;

    const int rowBase = blockIdx.y * 128;
    const int colBase = blockIdx.x * 128;

    int aR[4], aS[4], bR[4], bS[4], aC4[4], bC4[4];
#pragma unroll
    for (int i = 0; i < 4; i++) {
        int idx = tid + i * 256;
        int r  = idx >> 3;
        int c4 = (idx & 7) << 2;
        aR[i] = r; aS[i] = r * 32 + (c4 ^ ((r & 7) << 2)); aC4[i] = c4;
        int rb  = idx >> 5;
        int cb4 = (idx & 31) << 2;
        bR[i] = rb; bS[i] = rb * 136 + cb4; bC4[i] = cb4;
    }

    auto issue = [&](int t, int buf) {
        const int k0 = t * 32;
#pragma unroll
        for (int i = 0; i < 4; i++)
            cp16(smem_u32(&As[buf * A_TILE_U32 + aS[i]]),
                 &A[(size_t)(rowBase + aR[i]) * Kk + k0 + aC4[i]]);
#pragma unroll
        for (int i = 0; i < 4; i++)
            cp16(smem_u32(&Bs[buf * B_TILE_U32 + bS[i]]),
                 &Bw[(size_t)(k0 + bR[i]) * Nn + colBase + bC4[i]]);
        cp_commit();
    };

    float acc[2][8][4];
#pragma unroll
    for (int mt = 0; mt < 2; mt++)
#pragma unroll
        for (int nt = 0; nt < 8; nt++)
#pragma unroll
            for (int j = 0; j < 4; j++) acc[mt][nt][j] = 0.0f;

    const int T = Kk >> 5;
    issue(0, 0);
    issue(1, 1);

    for (int t = 0; t < T; t++) {
        if (t + 1 < T) cp_wait<1>(); else cp_wait<0>();
        __syncthreads();

        const int buf = t & 1;
        const uint32_t* Ab = &As[buf * A_TILE_U32];
        const uint32_t* Bb = &Bs[buf * B_TILE_U32];

#pragma unroll
        for (int kk = 0; kk < 32; kk += 8) {
            uint32_t a[2][4];
#pragma unroll
            for (int mt = 0; mt < 2; mt++) {
                const int m  = wm * 32 + mt * 16 + gid;
                const int sw = (m & 7) << 2;
                const int b0 = m * 32;
                const int b1 = b0 + 8 * 32;
                a[mt][0] = Ab[b0 + (kk ^ sw) + tig];
                a[mt][1] = Ab[b1 + (kk ^ sw) + tig];
                a[mt][2] = Ab[b0 + ((kk + 4) ^ sw) + tig];
                a[mt][3] = Ab[b1 + ((kk + 4) ^ sw) + tig];
            }
            uint32_t b[8][2];
#pragma unroll
            for (int nt = 0; nt < 8; nt++) {
                const int n = wn * 64 + nt * 8 + gid;
                b[nt][0] = Bb[(kk + tig) * 136 + n];
                b[nt][1] = Bb[(kk + tig + 4) * 136 + n];
            }
#pragma unroll
            for (int mt = 0; mt < 2; mt++)
#pragma unroll
                for (int nt = 0; nt < 8; nt++)
                    mma_tf32(acc[mt][nt], a[mt], b[nt]);
        }
        __syncthreads();
        if (t + 2 < T) issue(t + 2, buf);
    }

#pragma unroll
    for (int mt = 0; mt < 2; mt++) {
        const int row0 = rowBase + wm * 32 + mt * 16 + gid;
        const int row1 = row0 + 8;
#pragma unroll
        for (int nt = 0; nt < 8; nt++) {
            const int col = colBase + wn * 64 + nt * 8 + 2 * tig;
            float2 bb = *reinterpret_cast<const float2*>(&bias[col]);
            float v0 = acc[mt][nt][0] + bb.x;
            float v1 = acc[mt][nt][1] + bb.y;
            float v2 = acc[mt][nt][2] + bb.x;
            float v3 = acc[mt][nt][3] + bb.y;
            if (RELU) {
                v0 = fmaxf(v0, 0.0f); v1 = fmaxf(v1, 0.0f);
                v2 = fmaxf(v2, 0.0f); v3 = fmaxf(v3, 0.0f);
            }
            *reinterpret_cast<float2*>(&C[(size_t)row0 * Nn + col]) = make_float2(v0, v1);
            *reinterpret_cast<float2*>(&C[(size_t)row1 * Nn + col]) = make_float2(v2, v3);
        }
    }
}

__global__ __launch_bounds__(256, 2)
void qkv_kernel(const float* __restrict__ A,
                const float* __restrict__ Wq, const float* __restrict__ Wk,
                const float* __restrict__ Wv,
                const float* __restrict__ bq, const float* __restrict__ bk,
                const float* __restrict__ bv,
                float* __restrict__ Qo, float* __restrict__ Ko, float* __restrict__ Vo)
{
    const float* Bw; const float* bias; float* C;
    if (blockIdx.z == 0)      { Bw = Wq; bias = bq; C = Qo; }
    else if (blockIdx.z == 1) { Bw = Wk; bias = bk; C = Ko; }
    else                      { Bw = Wv; bias = bv; C = Vo; }
    gemm_body<false>(A, Bw, bias, C, D_, D_);
}

template <bool RELU>
__global__ __launch_bounds__(256, 2)
void ff_kernel(const float* __restrict__ A, const float* __restrict__ Bw,
               const float* __restrict__ bias, float* __restrict__ C,
               int Nn, int Kk)
{
    gemm_body<RELU>(A, Bw, bias, C, Nn, Kk);
}

// ----------------------------------------------------------------------------
// Attention prep: rewrite K' (augmented with coords) and V into the
// mma-fragment-tiled layout so the attention kernel can stage with cp.async.
// Grid: 512 blocks = (bh * 8 + ktile), 256 threads.
//
// K' layout per (bh, kt): idx = block32*32 + lane,
//   block32 = (kk>>2)*16 + (key>>3), lane = (kk&3)*8 + (key&7), kk in [0,40)
// V  layout per (bh, kt): block32 = (key>>2)*4 + (dk>>3), lane = (key&3)*8 + (dk&7)
// ----------------------------------------------------------------------------
__global__ __launch_bounds__(256)
void attn_prep_kernel(const float* __restrict__ K,
                      const float* __restrict__ V,
                      const float* __restrict__ coords,
                      float* __restrict__ Kaug,
                      float* __restrict__ Vaug)
{
    const int tid = threadIdx.x;
    const int bh  = blockIdx.x >> 3;
    const int kt  = blockIdx.x & 7;
    const int b   = bh >> 3;
    const int h   = bh & 7;

    const size_t kbase = (size_t)blockIdx.x * 5120;
#pragma unroll
    for (int j = 0; j < 20; j++) {
        const int idx = tid + j * 256;
        const int b32 = idx >> 5;
        const int ln  = idx & 31;
        const int kk  = (b32 >> 4) * 4 + (ln >> 3);
        const int key = (b32 & 15) * 8 + (ln & 7);
        const int row = b * N_ + kt * 128 + key;
        float val;
        if (kk < 32)      val = K[(size_t)row * D_ + h * DK_ + kk];
        else if (kk < 35) val = coords[(size_t)row * 3 + (kk - 32)];
        else              val = 0.0f;
        Kaug[kbase + idx] = val;
    }

    const size_t vbase = (size_t)blockIdx.x * 4096;
#pragma unroll
    for (int j = 0; j < 16; j++) {
        const int idx = tid + j * 256;
        const int b32 = idx >> 5;
        const int ln  = idx & 31;
        const int key = (b32 >> 2) * 4 + (ln >> 3);
        const int dk  = (b32 & 3) * 8 + (ln & 7);
        Vaug[vbase + idx] = V[((size_t)(b * N_ + kt * 128 + key)) * D_ + h * DK_ + dk];
    }
}

// ----------------------------------------------------------------------------
// tf32 MMA flash attention.
// Grid (B*H, N/128), 256 threads / 8 warps; warp w owns query rows w*16..+15.
// S = Q' @ K'^T over augmented DK'=40 (scale folded into Q, alpha*coords
// appended), online softmax on C fragments, P transposed to A fragments via
// quad shuffles, O += P @ V. K'/V tiles double-buffered via cp.async.
// ----------------------------------------------------------------------------
constexpr int KT_FLOATS   = 5120;
constexpr int VT_FLOATS   = 4096;
constexpr int TILE_FLOATS = KT_FLOATS + VT_FLOATS;           // 9216
constexpr int ATTN_SMEM   = 2 * TILE_FLOATS * 4;             // 73728 B

__global__ __launch_bounds__(256, 1)
void attn_mma_kernel(const float* __restrict__ Q,
                     const float* __restrict__ Kaug,
                     const float* __restrict__ Vaug,
                     const float* __restrict__ coords,
                     const float* __restrict__ alpha,
                     int layer,
                     float* __restrict__ Out)
{
    extern __shared__ float smf[];

    const int tid  = threadIdx.x;
    const int lane = tid & 31;
    const int w    = tid >> 5;
    const int gid  = lane >> 2;
    const int tig  = lane & 3;

    const int bh = blockIdx.x;
    const int b  = bh >> 3;
    const int h  = bh & 7;
    const int q0 = blockIdx.y * 128;

    const float scale  = 0.17677669529663687f;   // 1/sqrt(32)
    const float alphav = alpha[layer];

    // ---- load Q' fragments (augmented, scale/alpha folded in) ----
    uint32_t qf[5][4];
    {
        const int row0 = b * N_ + q0 + w * 16 + gid;
#pragma unroll
        for (int ks = 0; ks < 5; ks++) {
#pragma unroll
            for (int r = 0; r < 4; r++) {
                const int row = row0 + (r & 1) * 8;
                const int kk  = ks * 8 + tig + ((r >> 1) << 2);
                float v;
                if (kk < 32)      v = Q[(size_t)row * D_ + h * DK_ + kk] * scale;
                else if (kk < 35) v = alphav * coords[(size_t)row * 3 + (kk - 32)];
                else              v = 0.0f;
                qf[ks][r] = __float_as_uint(v);
            }
        }
    }

    // ---- staging ----
    auto issue = [&](int t, int buf) {
        const float* srcK = Kaug + (size_t)(bh * 8 + t) * KT_FLOATS;
        float* dstK = smf + buf * TILE_FLOATS;
#pragma unroll
        for (int j = 0; j < 5; j++) {
            const int i16 = tid + j * 256;
            cp16(smem_u32(dstK + i16 * 4), srcK + i16 * 4);
        }
        const float* srcV = Vaug + (size_t)(bh * 8 + t) * VT_FLOATS;
        float* dstV = smf + buf * TILE_FLOATS + KT_FLOATS;
#pragma unroll
        for (int j = 0; j < 4; j++) {
            const int i16 = tid + j * 256;
            cp16(smem_u32(dstV + i16 * 4), srcV + i16 * 4);
        }
        cp_commit();
    };

    float O[4][4];
#pragma unroll
    for (int i = 0; i < 4; i++)
#pragma unroll
        for (int j = 0; j < 4; j++) O[i][j] = 0.0f;
    float m0 = -1e30f, m1 = -1e30f, l0 = 0.0f, l1 = 0.0f;

    const int klane = tig * 8 + gid;
    const int src0  = (gid << 2) + (tig >> 1);
    const int src1  = src0 + 2;

    issue(0, 0);

    for (int t = 0; t < 8; t++) {
        if (t < 7) { issue(t + 1, (t + 1) & 1); cp_wait<1>(); }
        else       { cp_wait<0>(); }
        __syncthreads();

        const uint32_t* Kb = reinterpret_cast<const uint32_t*>(smf + (t & 1) * TILE_FLOATS);
        const uint32_t* Vb = Kb + KT_FLOATS;

        // ---- S = Q' @ K'^T  (16 n-tiles x 5 k-steps) ----
        float s[16][4];
#pragma unroll
        for (int nt = 0; nt < 16; nt++)
#pragma unroll
            for (int j = 0; j < 4; j++) s[nt][j] = 0.0f;

#pragma unroll
        for (int ks = 0; ks < 5; ks++) {
#pragma unroll
            for (int nt = 0; nt < 16; nt++) {
                uint32_t bfr[2];
                bfr[0] = Kb[(32 * ks + nt) * 32 + klane];
                bfr[1] = Kb[(32 * ks + 16 + nt) * 32 + klane];
                mma_tf32(s[nt], qf[ks], bfr);
            }
        }

        // ---- online softmax on C fragments ----
        float mx0 = -1e30f, mx1 = -1e30f;
#pragma unroll
        for (int nt = 0; nt < 16; nt++) {
            mx0 = fmaxf(mx0, fmaxf(s[nt][0], s[nt][1]));
            mx1 = fmaxf(mx1, fmaxf(s[nt][2], s[nt][3]));
        }
        mx0 = fmaxf(mx0, __shfl_xor_sync(0xffffffffu, mx0, 1));
        mx0 = fmaxf(mx0, __shfl_xor_sync(0xffffffffu, mx0, 2));
        mx1 = fmaxf(mx1, __shfl_xor_sync(0xffffffffu, mx1, 1));
        mx1 = fmaxf(mx1, __shfl_xor_sync(0xffffffffu, mx1, 2));

        const float mn0 = fmaxf(m0, mx0);
        const float mn1 = fmaxf(m1, mx1);
        const float c0  = __expf(m0 - mn0);
        const float c1  = __expf(m1 - mn1);
        m0 = mn0; m1 = mn1;

        float rs0 = 0.0f, rs1 = 0.0f;
#pragma unroll
        for (int nt = 0; nt < 16; nt++) {
            s[nt][0] = __expf(s[nt][0] - mn0);
            s[nt][1] = __expf(s[nt][1] - mn0);
            s[nt][2] = __expf(s[nt][2] - mn1);
            s[nt][3] = __expf(s[nt][3] - mn1);
            rs0 += s[nt][0] + s[nt][1];
            rs1 += s[nt][2] + s[nt][3];
        }
        rs0 += __shfl_xor_sync(0xffffffffu, rs0, 1);
        rs0 += __shfl_xor_sync(0xffffffffu, rs0, 2);
        rs1 += __shfl_xor_sync(0xffffffffu, rs1, 1);
        rs1 += __shfl_xor_sync(0xffffffffu, rs1, 2);
        l0 = l0 * c0 + rs0;
        l1 = l1 * c1 + rs1;

#pragma unroll
        for (int nt2 = 0; nt2 < 4; nt2++) {
            O[nt2][0] *= c0; O[nt2][1] *= c0;
            O[nt2][2] *= c1; O[nt2][3] *= c1;
        }

        // ---- O += P @ V  (16 k-steps over keys, 4 dk n-tiles) ----
#pragma unroll
        for (int ks = 0; ks < 16; ks++) {
            // transpose P C-fragment -> A-fragment via quad shuffles
            uint32_t a[4];
            {
                float v0 = __shfl_sync(0xffffffffu, s[ks][0], src0);
                float v1 = __shfl_sync(0xffffffffu, s[ks][1], src0);
                float v2 = __shfl_sync(0xffffffffu, s[ks][2], src0);
                float v3 = __shfl_sync(0xffffffffu, s[ks][3], src0);
                float u0 = __shfl_sync(0xffffffffu, s[ks][0], src1);
                float u1 = __shfl_sync(0xffffffffu, s[ks][1], src1);
                float u2 = __shfl_sync(0xffffffffu, s[ks][2], src1);
                float u3 = __shfl_sync(0xffffffffu, s[ks][3], src1);
                const bool odd = (tig & 1);
                a[0] = __float_as_uint(odd ? v1 : v0);
                a[1] = __float_as_uint(odd ? v3 : v2);
                a[2] = __float_as_uint(odd ? u1 : u0);
                a[3] = __float_as_uint(odd ? u3 : u2);
            }
#pragma unroll
            for (int nt2 = 0; nt2 < 4; nt2++) {
                uint32_t bfr[2];
                bfr[0] = Vb[(8 * ks + nt2) * 32 + klane];
                bfr[1] = Vb[(8 * ks + 4 + nt2) * 32 + klane];
                mma_tf32(O[nt2], a, bfr);
            }
        }
        __syncthreads();
    }

    // ---- finalize & store ----
    const float inv0 = 1.0f / l0;
    const float inv1 = 1.0f / l1;
    const int row0 = b * N_ + q0 + w * 16 + gid;
    const int row1 = row0 + 8;
#pragma unroll
    for (int nt2 = 0; nt2 < 4; nt2++) {
        const int col = h * DK_ + nt2 * 8 + 2 * tig;
        *reinterpret_cast<float2*>(&Out[(size_t)row0 * D_ + col]) =
            make_float2(O[nt2][0] * inv0, O[nt2][1] * inv0);
        *reinterpret_cast<float2*>(&Out[(size_t)row1 * D_ + col]) =
            make_float2(O[nt2][2] * inv1, O[nt2][3] * inv1);
    }
}

// ----------------------------------------------------------------------------
// Fused residual add + LayerNorm. Warp per row.
// ----------------------------------------------------------------------------
__global__ __launch_bounds__(256, 6)
void add_ln_kernel(const float* __restrict__ x,
                   const float* __restrict__ delta,
                   const float* __restrict__ g,
                   const float* __restrict__ be,
                   float* __restrict__ out)
{
    const int warp = threadIdx.x >> 5;
    const int lane = threadIdx.x & 31;
    const int row  = blockIdx.x * 8 + warp;
    const int col0 = lane * 8;

    const float4* xr = reinterpret_cast<const float4*>(&x[(size_t)row * D_ + col0]);
    const float4* dr = reinterpret_cast<const float4*>(&delta[(size_t)row * D_ + col0]);

    float r[8];
    {
        float4 a0 = xr[0], a1 = xr[1], b0 = dr[0], b1 = dr[1];
        r[0] = a0.x + b0.x; r[1] = a0.y + b0.y; r[2] = a0.z + b0.z; r[3] = a0.w + b0.w;
        r[4] = a1.x + b1.x; r[5] = a1.y + b1.y; r[6] = a1.z + b1.z; r[7] = a1.w + b1.w;
    }

    float s = 0.0f;
#pragma unroll
    for (int j = 0; j < 8; j++) s += r[j];
#pragma unroll
    for (int off = 16; off > 0; off >>= 1) s += __shfl_xor_sync(0xffffffffu, s, off);
    const float mean = s * (1.0f / 256.0f);

    float v = 0.0f;
#pragma unroll
    for (int j = 0; j < 8; j++) { float t = r[j] - mean; v = fmaf(t, t, v); }
#pragma unroll
    for (int off = 16; off > 0; off >>= 1) v += __shfl_xor_sync(0xffffffffu, v, off);
    const float rs = rsqrtf(v * (1.0f / 256.0f) + 1e-5f);

    const float4* gg = reinterpret_cast<const float4*>(&g[col0]);
    const float4* bb = reinterpret_cast<const float4*>(&be[col0]);
    float4 g0 = gg[0], g1 = gg[1], e0 = bb[0], e1 = bb[1];

    float4 o0, o1;
    o0.x = (r[0] - mean) * rs * g0.x + e0.x;
    o0.y = (r[1] - mean) * rs * g0.y + e0.y;
    o0.z = (r[2] - mean) * rs * g0.z + e0.z;
    o0.w = (r[3] - mean) * rs * g0.w + e0.w;
    o1.x = (r[4] - mean) * rs * g1.x + e1.x;
    o1.y = (r[5] - mean) * rs * g1.y + e1.y;
    o1.z = (r[6] - mean) * rs * g1.z + e1.z;
    o1.w = (r[7] - mean) * rs * g1.w + e1.w;

    float4* orow = reinterpret_cast<float4*>(&out[(size_t)row * D_ + col0]);
    orow[0] = o0;
    orow[1] = o1;
}

// ----------------------------------------------------------------------------
// Host driver
// ----------------------------------------------------------------------------
extern "C" void kernel_launch(void* const* d_in, const int* in_sizes, int n_in,
                              void* d_out, int out_size)
{
    const float* x      = (const float*)d_in[0];
    const float* coords = (const float*)d_in[1];
    const float* Wq     = (const float*)d_in[2];
    const float* bq     = (const float*)d_in[3];
    const float* Wk     = (const float*)d_in[4];
    const float* bk     = (const float*)d_in[5];
    const float* Wv     = (const float*)d_in[6];
    const float* bv     = (const float*)d_in[7];
    const float* alpha  = (const float*)d_in[8];
    const float* W1     = (const float*)d_in[9];
    const float* b1     = (const float*)d_in[10];
    const float* W2     = (const float*)d_in[11];
    const float* b2     = (const float*)d_in[12];
    const float* g1     = (const float*)d_in[13];
    const float* be1    = (const float*)d_in[14];
    const float* g2     = (const float*)d_in[15];
    const float* be2    = (const float*)d_in[16];
    float* out = (float*)d_out;

    float *Qp, *Kp, *Vp, *Ap, *Xp, *Hp, *Fp, *KAp, *VAp;
    cudaGetSymbolAddress((void**)&Qp,  g_Q);
    cudaGetSymbolAddress((void**)&Kp,  g_K);
    cudaGetSymbolAddress((void**)&Vp,  g_V);
    cudaGetSymbolAddress((void**)&Ap,  g_ATT);
    cudaGetSymbolAddress((void**)&Xp,  g_X);
    cudaGetSymbolAddress((void**)&Hp,  g_Hb);
    cudaGetSymbolAddress((void**)&Fp,  g_Fb);
    cudaGetSymbolAddress((void**)&KAp, g_Kaug);
    cudaGetSymbolAddress((void**)&VAp, g_Vaug);

    cudaFuncSetAttribute(qkv_kernel,
                         cudaFuncAttributeMaxDynamicSharedMemorySize, GEMM_SMEM);
    cudaFuncSetAttribute(ff_kernel<true>,
                         cudaFuncAttributeMaxDynamicSharedMemorySize, GEMM_SMEM);
    cudaFuncSetAttribute(ff_kernel<false>,
                         cudaFuncAttributeMaxDynamicSharedMemorySize, GEMM_SMEM);
    cudaFuncSetAttribute(attn_mma_kernel,
                         cudaFuncAttributeMaxDynamicSharedMemorySize, ATTN_SMEM);

    const dim3 gQKV(D_ / 128, ROWS / 128, 3);  // (2, 64, 3)
    const dim3 gFF1(FF_ / 128, ROWS / 128);    // (8, 64)
    const dim3 gFF2(D_ / 128, ROWS / 128);     // (2, 64)
    const dim3 gAttn(B_ * H_, N_ / 128);       // (64, 8)

    const float* cur = x;
    for (int i = 0; i < L_; i++) {
        qkv_kernel<<<gQKV, 256, GEMM_SMEM>>>(
            cur,
            Wq + (size_t)i * D_ * D_, Wk + (size_t)i * D_ * D_, Wv + (size_t)i * D_ * D_,
            bq + i * D_, bk + i * D_, bv + i * D_,
            Qp, Kp, Vp);

        attn_prep_kernel<<<512, 256>>>(Kp, Vp, coords, KAp, VAp);

        attn_mma_kernel<<<gAttn, 256, ATTN_SMEM>>>(Qp, KAp, VAp, coords, alpha, i, Ap);

        add_ln_kernel<<<ROWS / 8, 256>>>(cur, Ap, g1 + i * D_, be1 + i * D_, Xp);

        ff_kernel<true ><<<gFF1, 256, GEMM_SMEM>>>(Xp, W1 + (size_t)i * D_ * FF_,
                                                   b1 + i * FF_, Hp, FF_, D_);
        ff_kernel<false><<<gFF2, 256, GEMM_SMEM>>>(Hp, W2 + (size_t)i * FF_ * D_,
                                                   b2 + i * D_, Fp, D_, FF_);

        float* xo = (i == L_ - 1) ? out : Xp;
        add_ln_kernel<<<ROWS / 8, 256>>>(Xp, Fp, g2 + i * D_, be2 + i * D_, xo);

        cur = Xp;
    }
}

// round 9
// speedup vs baseline: 5.0032x; 1.0498x over previous
#include <cuda_runtime.h>
#include <cstdint>

// ----------------------------------------------------------------------------
// Problem constants
// ----------------------------------------------------------------------------
constexpr int B_  = 8;
constexpr int N_  = 1024;
constexpr int D_  = 256;
constexpr int H_  = 8;
constexpr int DK_ = 32;
constexpr int FF_ = 1024;
constexpr int L_  = 4;
constexpr int ROWS = B_ * N_;          // 8192 token rows

// ----------------------------------------------------------------------------
// Scratch (device globals: no allocation allowed)
// ----------------------------------------------------------------------------
__device__ float g_Q  [ROWS * D_];
__device__ float g_ATT[ROWS * D_];
__device__ float g_X  [ROWS * D_];
__device__ float g_Hb [ROWS * FF_];
__device__ float g_Fb [ROWS * D_];
// Attention staging buffers in mma-fragment-tiled layout.
// K' : per (bh, ktile): 40 kk x 128 keys -> 5120 floats (kk>=32 = coords rows)
// V  : per (bh, ktile): 128 keys x 32 dk -> 4096 floats
__device__ __align__(16) float g_Kaug[64 * 8 * 5120];
__device__ __align__(16) float g_Vaug[64 * 8 * 4096];

// ----------------------------------------------------------------------------
// Helpers
// ----------------------------------------------------------------------------
__device__ __forceinline__ uint32_t smem_u32(const void* p) {
    return (uint32_t)__cvta_generic_to_shared(p);
}
__device__ __forceinline__ void cp16(uint32_t s, const void* g) {
    asm volatile("cp.async.cg.shared.global [%0], [%1], 16;" :: "r"(s), "l"(g));
}
__device__ __forceinline__ void cp_commit() {
    asm volatile("cp.async.commit_group;" ::: "memory");
}
template <int NN>
__device__ __forceinline__ void cp_wait() {
    asm volatile("cp.async.wait_group %0;" :: "n"(NN) : "memory");
}
__device__ __forceinline__ void mma_tf32(float* c, const uint32_t* a, const uint32_t* b) {
    asm volatile(
        "mma.sync.aligned.m16n8k8.row.col.f32.tf32.tf32.f32 "
        "{%0,%1,%2,%3},{%4,%5,%6,%7},{%8,%9},{%0,%1,%2,%3};"
        : "+f"(c[0]), "+f"(c[1]), "+f"(c[2]), "+f"(c[3])
        : "r"(a[0]), "r"(a[1]), "r"(a[2]), "r"(a[3]), "r"(b[0]), "r"(b[1]));
}

// ----------------------------------------------------------------------------
// tf32 MMA GEMM core: acc = A[128 rows] @ Bw[:,128 cols], 3-stage cp.async
// pipeline, ONE barrier per k-tile. CTA 128x128, BK=32, 8 warps (4x2).
// ----------------------------------------------------------------------------
constexpr int A_TILE_U32 = 128 * 32;
constexpr int B_TILE_U32 = 32 * 136;
constexpr int STAGE_U32  = A_TILE_U32 + B_TILE_U32;            // 8448
constexpr int GEMM_SMEM  = 3 * STAGE_U32 * 4;                  // 101376 bytes

__device__ __forceinline__ void gemm_accum(const float* __restrict__ A,
                                           const float* __restrict__ Bw,
                                           int Nn, int Kk,
                                           float acc[2][8][4])
{
    extern __shared__ uint32_t sm[];

    const int tid  = threadIdx.x;
    const int lane = tid & 31;
    const int warp = tid >> 5;
    const int gid  = lane >> 2;
    const int tig  = lane & 3;
    const int wm   = warp & 3;
    const int wn   = warp >> 2;

    const int rowBase = blockIdx.y * 128;
    const int colBase = blockIdx.x * 128;

    int aR[4], aS[4], bR[4], bS[4], aC4[4], bC4[4];
#pragma unroll
    for (int i = 0; i < 4; i++) {
        int idx = tid + i * 256;
        int r  = idx >> 3;
        int c4 = (idx & 7) << 2;
        aR[i] = r; aS[i] = r * 32 + (c4 ^ ((r & 7) << 2)); aC4[i] = c4;
        int rb  = idx >> 5;
        int cb4 = (idx & 31) << 2;
        bR[i] = rb; bS[i] = rb * 136 + cb4; bC4[i] = cb4;
    }

    auto issue = [&](int t, int buf) {
        const int k0 = t * 32;
        uint32_t* As = sm + buf * STAGE_U32;
        uint32_t* Bs = As + A_TILE_U32;
#pragma unroll
        for (int i = 0; i < 4; i++)
            cp16(smem_u32(&As[aS[i]]),
                 &A[(size_t)(rowBase + aR[i]) * Kk + k0 + aC4[i]]);
#pragma unroll
        for (int i = 0; i < 4; i++)
            cp16(smem_u32(&Bs[bS[i]]),
                 &Bw[(size_t)(k0 + bR[i]) * Nn + colBase + bC4[i]]);
        cp_commit();
    };

#pragma unroll
    for (int mt = 0; mt < 2; mt++)
#pragma unroll
        for (int nt = 0; nt < 8; nt++)
#pragma unroll
            for (int j = 0; j < 4; j++) acc[mt][nt][j] = 0.0f;

    const int T = Kk >> 5;
    issue(0, 0);
    issue(1, 1);

    int buf = 0;
    for (int t = 0; t < T; t++) {
        if (t + 1 < T) cp_wait<1>(); else cp_wait<0>();
        __syncthreads();

        const uint32_t* Ab = sm + buf * STAGE_U32;
        const uint32_t* Bb = Ab + A_TILE_U32;

#pragma unroll
        for (int kk = 0; kk < 32; kk += 8) {
            uint32_t a[2][4];
#pragma unroll
            for (int mt = 0; mt < 2; mt++) {
                const int m  = wm * 32 + mt * 16 + gid;
                const int sw = (m & 7) << 2;
                const int b0 = m * 32;
                const int b1 = b0 + 8 * 32;
                a[mt][0] = Ab[b0 + (kk ^ sw) + tig];
                a[mt][1] = Ab[b1 + (kk ^ sw) + tig];
                a[mt][2] = Ab[b0 + ((kk + 4) ^ sw) + tig];
                a[mt][3] = Ab[b1 + ((kk + 4) ^ sw) + tig];
            }
            uint32_t b[8][2];
#pragma unroll
            for (int nt = 0; nt < 8; nt++) {
                const int n = wn * 64 + nt * 8 + gid;
                b[nt][0] = Bb[(kk + tig) * 136 + n];
                b[nt][1] = Bb[(kk + tig + 4) * 136 + n];
            }
#pragma unroll
            for (int mt = 0; mt < 2; mt++)
#pragma unroll
                for (int nt = 0; nt < 8; nt++)
                    mma_tf32(acc[mt][nt], a[mt], b[nt]);
        }

        // safe: barrier above guarantees all warps finished stage (t-1),
        // whose buffer is exactly (t+2) % 3.
        if (t + 2 < T) {
            int nbuf = buf + 2; if (nbuf >= 3) nbuf -= 3;
            issue(t + 2, nbuf);
        }
        if (++buf == 3) buf = 0;
    }
}

// ----------------------------------------------------------------------------
// QKV kernel. z=0: Q -> g_Q (plain layout). z=1: K -> g_Kaug (fragment-tiled,
// kk<32 part). z=2: V -> g_Vaug (fragment-tiled).
// ----------------------------------------------------------------------------
__global__ __launch_bounds__(256, 2)
void qkv_kernel(const float* __restrict__ A,
                const float* __restrict__ Wq, const float* __restrict__ Wk,
                const float* __restrict__ Wv,
                const float* __restrict__ bq, const float* __restrict__ bk,
                const float* __restrict__ bv,
                float* __restrict__ Qo, float* __restrict__ Kaug,
                float* __restrict__ Vaug)
{
    const float* Bw; const float* bias;
    if (blockIdx.z == 0)      { Bw = Wq; bias = bq; }
    else if (blockIdx.z == 1) { Bw = Wk; bias = bk; }
    else                      { Bw = Wv; bias = bv; }

    float acc[2][8][4];
    gemm_accum(A, Bw, D_, D_, acc);

    const int lane = threadIdx.x & 31;
    const int warp = threadIdx.x >> 5;
    const int gid  = lane >> 2;
    const int tig  = lane & 3;
    const int wm   = warp & 3;
    const int wn   = warp >> 2;
    const int rowBase = blockIdx.y * 128;
    const int colBase = blockIdx.x * 128;

    if (blockIdx.z == 0) {
#pragma unroll
        for (int mt = 0; mt < 2; mt++) {
            const int row0 = rowBase + wm * 32 + mt * 16 + gid;
            const int row1 = row0 + 8;
#pragma unroll
            for (int nt = 0; nt < 8; nt++) {
                const int col = colBase + wn * 64 + nt * 8 + 2 * tig;
                float2 bb = *reinterpret_cast<const float2*>(&bias[col]);
                *reinterpret_cast<float2*>(&Qo[(size_t)row0 * D_ + col]) =
                    make_float2(acc[mt][nt][0] + bb.x, acc[mt][nt][1] + bb.y);
                *reinterpret_cast<float2*>(&Qo[(size_t)row1 * D_ + col]) =
                    make_float2(acc[mt][nt][2] + bb.x, acc[mt][nt][3] + bb.y);
            }
        }
    } else if (blockIdx.z == 1) {
        // K -> Kaug: addr = ((b*8+h)*8+kt)*5120 + ((kk>>2)*16+(key>>3))*32
        //                  + (kk&3)*8 + (key&7)
#pragma unroll
        for (int mt = 0; mt < 2; mt++) {
            const int row0 = rowBase + wm * 32 + mt * 16 + gid;
            const int b    = row0 >> 10;
            const int n0   = row0 & 1023;
            const int kt   = n0 >> 7;
            const int key0 = n0 & 127;
            const int key1 = key0 + 8;
#pragma unroll
            for (int nt = 0; nt < 8; nt++) {
                const int col = colBase + wn * 64 + nt * 8 + 2 * tig;
                const int h   = col >> 5;
                const int kk0 = col & 31;
                float2 bb = *reinterpret_cast<const float2*>(&bias[col]);
                const size_t base = (size_t)((b * 8 + h) * 8 + kt) * 5120;
#pragma unroll
                for (int e = 0; e < 4; e++) {
                    const int kk  = kk0 + (e & 1);
                    const int key = (e < 2) ? key0 : key1;
                    const float v = acc[mt][nt][e] + ((e & 1) ? bb.y : bb.x);
                    Kaug[base + (size_t)(((kk >> 2) * 16 + (key >> 3)) * 32
                                         + (kk & 3) * 8 + (key & 7))] = v;
                }
            }
        }
    } else {
        // V -> Vaug: addr = ((b*8+h)*8+kt)*4096 + ((key>>2)*4+(dk>>3))*32
        //                  + (key&3)*8 + (dk&7)
#pragma unroll
        for (int mt = 0; mt < 2; mt++) {
            const int row0 = rowBase + wm * 32 + mt * 16 + gid;
            const int b    = row0 >> 10;
            const int n0   = row0 & 1023;
            const int kt   = n0 >> 7;
            const int key0 = n0 & 127;
            const int key1 = key0 + 8;
#pragma unroll
            for (int nt = 0; nt < 8; nt++) {
                const int col = colBase + wn * 64 + nt * 8 + 2 * tig;
                const int h   = col >> 5;
                const int dk0 = col & 31;
                float2 bb = *reinterpret_cast<const float2*>(&bias[col]);
                const size_t base = (size_t)((b * 8 + h) * 8 + kt) * 4096;
#pragma unroll
                for (int e = 0; e < 4; e++) {
                    const int dk  = dk0 + (e & 1);
                    const int key = (e < 2) ? key0 : key1;
                    const float v = acc[mt][nt][e] + ((e & 1) ? bb.y : bb.x);
                    Vaug[base + (size_t)(((key >> 2) * 4 + (dk >> 3)) * 32
                                         + (key & 3) * 8 + (dk & 7))] = v;
                }
            }
        }
    }
}

template <bool RELU>
__global__ __launch_bounds__(256, 2)
void ff_kernel(const float* __restrict__ A, const float* __restrict__ Bw,
               const float* __restrict__ bias, float* __restrict__ C,
               int Nn, int Kk)
{
    float acc[2][8][4];
    gemm_accum(A, Bw, Nn, Kk, acc);

    const int lane = threadIdx.x & 31;
    const int warp = threadIdx.x >> 5;
    const int gid  = lane >> 2;
    const int tig  = lane & 3;
    const int wm   = warp & 3;
    const int wn   = warp >> 2;
    const int rowBase = blockIdx.y * 128;
    const int colBase = blockIdx.x * 128;

#pragma unroll
    for (int mt = 0; mt < 2; mt++) {
        const int row0 = rowBase + wm * 32 + mt * 16 + gid;
        const int row1 = row0 + 8;
#pragma unroll
        for (int nt = 0; nt < 8; nt++) {
            const int col = colBase + wn * 64 + nt * 8 + 2 * tig;
            float2 bb = *reinterpret_cast<const float2*>(&bias[col]);
            float v0 = acc[mt][nt][0] + bb.x;
            float v1 = acc[mt][nt][1] + bb.y;
            float v2 = acc[mt][nt][2] + bb.x;
            float v3 = acc[mt][nt][3] + bb.y;
            if (RELU) {
                v0 = fmaxf(v0, 0.0f); v1 = fmaxf(v1, 0.0f);
                v2 = fmaxf(v2, 0.0f); v3 = fmaxf(v3, 0.0f);
            }
            *reinterpret_cast<float2*>(&C[(size_t)row0 * Nn + col]) = make_float2(v0, v1);
            *reinterpret_cast<float2*>(&C[(size_t)row1 * Nn + col]) = make_float2(v2, v3);
        }
    }
}

// ----------------------------------------------------------------------------
// One-time fill of Kaug coords rows (kk 32..39): layer-invariant.
// Grid 512 = (bh*8 + kt), 256 threads, 4 floats each (1024 per tile).
// ----------------------------------------------------------------------------
__global__ __launch_bounds__(256)
void fill_kcoords_kernel(const float* __restrict__ coords,
                         float* __restrict__ Kaug)
{
    const int t  = blockIdx.x;
    const int bh = t >> 3;
    const int kt = t & 7;
    const int b  = bh >> 3;
    const size_t base = (size_t)t * 5120 + 128 * 32;
#pragma unroll
    for (int j = 0; j < 4; j++) {
        const int e   = threadIdx.x + j * 256;       // 0..1023
        const int rel = e >> 5;                      // 0..31
        const int ln  = e & 31;
        const int kk  = 32 + (rel >> 4) * 4 + (ln >> 3);
        const int key = (rel & 15) * 8 + (ln & 7);
        float v = 0.0f;
        if (kk < 35)
            v = coords[(size_t)(b * N_ + kt * 128 + key) * 3 + (kk - 32)];
        Kaug[base + e] = v;
    }
}

// ----------------------------------------------------------------------------
// tf32 MMA flash attention (unchanged from R4/R7).
// ----------------------------------------------------------------------------
constexpr int KT_FLOATS   = 5120;
constexpr int VT_FLOATS   = 4096;
constexpr int TILE_FLOATS = KT_FLOATS + VT_FLOATS;
constexpr int ATTN_SMEM   = 2 * TILE_FLOATS * 4;

__global__ __launch_bounds__(256, 1)
void attn_mma_kernel(const float* __restrict__ Q,
                     const float* __restrict__ Kaug,
                     const float* __restrict__ Vaug,
                     const float* __restrict__ coords,
                     const float* __restrict__ alpha,
                     int layer,
                     float* __restrict__ Out)
{
    extern __shared__ float smf[];

    const int tid  = threadIdx.x;
    const int lane = tid & 31;
    const int w    = tid >> 5;
    const int gid  = lane >> 2;
    const int tig  = lane & 3;

    const int bh = blockIdx.x;
    const int b  = bh >> 3;
    const int h  = bh & 7;
    const int q0 = blockIdx.y * 128;

    const float scale  = 0.17677669529663687f;
    const float alphav = alpha[layer];

    uint32_t qf[5][4];
    {
        const int row0 = b * N_ + q0 + w * 16 + gid;
#pragma unroll
        for (int ks = 0; ks < 5; ks++) {
#pragma unroll
            for (int r = 0; r < 4; r++) {
                const int row = row0 + (r & 1) * 8;
                const int kk  = ks * 8 + tig + ((r >> 1) << 2);
                float v;
                if (kk < 32)      v = Q[(size_t)row * D_ + h * DK_ + kk] * scale;
                else if (kk < 35) v = alphav * coords[(size_t)row * 3 + (kk - 32)];
                else              v = 0.0f;
                qf[ks][r] = __float_as_uint(v);
            }
        }
    }

    auto issue = [&](int t, int buf) {
        const float* srcK = Kaug + (size_t)(bh * 8 + t) * KT_FLOATS;
        float* dstK = smf + buf * TILE_FLOATS;
#pragma unroll
        for (int j = 0; j < 5; j++) {
            const int i16 = tid + j * 256;
            cp16(smem_u32(dstK + i16 * 4), srcK + i16 * 4);
        }
        const float* srcV = Vaug + (size_t)(bh * 8 + t) * VT_FLOATS;
        float* dstV = smf + buf * TILE_FLOATS + KT_FLOATS;
#pragma unroll
        for (int j = 0; j < 4; j++) {
            const int i16 = tid + j * 256;
            cp16(smem_u32(dstV + i16 * 4), srcV + i16 * 4);
        }
        cp_commit();
    };

    float O[4][4];
#pragma unroll
    for (int i = 0; i < 4; i++)
#pragma unroll
        for (int j = 0; j < 4; j++) O[i][j] = 0.0f;
    float m0 = -1e30f, m1 = -1e30f, l0 = 0.0f, l1 = 0.0f;

    const int klane = tig * 8 + gid;
    const int src0  = (gid << 2) + (tig >> 1);
    const int src1  = src0 + 2;

    issue(0, 0);

    for (int t = 0; t < 8; t++) {
        if (t < 7) { issue(t + 1, (t + 1) & 1); cp_wait<1>(); }
        else       { cp_wait<0>(); }
        __syncthreads();

        const uint32_t* Kb = reinterpret_cast<const uint32_t*>(smf + (t & 1) * TILE_FLOATS);
        const uint32_t* Vb = Kb + KT_FLOATS;

        float s[16][4];
#pragma unroll
        for (int nt = 0; nt < 16; nt++)
#pragma unroll
            for (int j = 0; j < 4; j++) s[nt][j] = 0.0f;

#pragma unroll
        for (int ks = 0; ks < 5; ks++) {
#pragma unroll
            for (int nt = 0; nt < 16; nt++) {
                uint32_t bfr[2];
                bfr[0] = Kb[(32 * ks + nt) * 32 + klane];
                bfr[1] = Kb[(32 * ks + 16 + nt) * 32 + klane];
                mma_tf32(s[nt], qf[ks], bfr);
            }
        }

        float mx0 = -1e30f, mx1 = -1e30f;
#pragma unroll
        for (int nt = 0; nt < 16; nt++) {
            mx0 = fmaxf(mx0, fmaxf(s[nt][0], s[nt][1]));
            mx1 = fmaxf(mx1, fmaxf(s[nt][2], s[nt][3]));
        }
        mx0 = fmaxf(mx0, __shfl_xor_sync(0xffffffffu, mx0, 1));
        mx0 = fmaxf(mx0, __shfl_xor_sync(0xffffffffu, mx0, 2));
        mx1 = fmaxf(mx1, __shfl_xor_sync(0xffffffffu, mx1, 1));
        mx1 = fmaxf(mx1, __shfl_xor_sync(0xffffffffu, mx1, 2));

        const float mn0 = fmaxf(m0, mx0);
        const float mn1 = fmaxf(m1, mx1);
        const float c0  = __expf(m0 - mn0);
        const float c1  = __expf(m1 - mn1);
        m0 = mn0; m1 = mn1;

        float rs0 = 0.0f, rs1 = 0.0f;
#pragma unroll
        for (int nt = 0; nt < 16; nt++) {
            s[nt][0] = __expf(s[nt][0] - mn0);
            s[nt][1] = __expf(s[nt][1] - mn0);
            s[nt][2] = __expf(s[nt][2] - mn1);
            s[nt][3] = __expf(s[nt][3] - mn1);
            rs0 += s[nt][0] + s[nt][1];
            rs1 += s[nt][2] + s[nt][3];
        }
        rs0 += __shfl_xor_sync(0xffffffffu, rs0, 1);
        rs0 += __shfl_xor_sync(0xffffffffu, rs0, 2);
        rs1 += __shfl_xor_sync(0xffffffffu, rs1, 1);
        rs1 += __shfl_xor_sync(0xffffffffu, rs1, 2);
        l0 = l0 * c0 + rs0;
        l1 = l1 * c1 + rs1;

#pragma unroll
        for (int nt2 = 0; nt2 < 4; nt2++) {
            O[nt2][0] *= c0; O[nt2][1] *= c0;
            O[nt2][2] *= c1; O[nt2][3] *= c1;
        }

#pragma unroll
        for (int ks = 0; ks < 16; ks++) {
            uint32_t a[4];
            {
                float v0 = __shfl_sync(0xffffffffu, s[ks][0], src0);
                float v1 = __shfl_sync(0xffffffffu, s[ks][1], src0);
                float v2 = __shfl_sync(0xffffffffu, s[ks][2], src0);
                float v3 = __shfl_sync(0xffffffffu, s[ks][3], src0);
                float u0 = __shfl_sync(0xffffffffu, s[ks][0], src1);
                float u1 = __shfl_sync(0xffffffffu, s[ks][1], src1);
                float u2 = __shfl_sync(0xffffffffu, s[ks][2], src1);
                float u3 = __shfl_sync(0xffffffffu, s[ks][3], src1);
                const bool odd = (tig & 1);
                a[0] = __float_as_uint(odd ? v1 : v0);
                a[1] = __float_as_uint(odd ? v3 : v2);
                a[2] = __float_as_uint(odd ? u1 : u0);
                a[3] = __float_as_uint(odd ? u3 : u2);
            }
#pragma unroll
            for (int nt2 = 0; nt2 < 4; nt2++) {
                uint32_t bfr[2];
                bfr[0] = Vb[(8 * ks + nt2) * 32 + klane];
                bfr[1] = Vb[(8 * ks + 4 + nt2) * 32 + klane];
                mma_tf32(O[nt2], a, bfr);
            }
        }
        __syncthreads();
    }

    const float inv0 = 1.0f / l0;
    const float inv1 = 1.0f / l1;
    const int row0 = b * N_ + q0 + w * 16 + gid;
    const int row1 = row0 + 8;
#pragma unroll
    for (int nt2 = 0; nt2 < 4; nt2++) {
        const int col = h * DK_ + nt2 * 8 + 2 * tig;
        *reinterpret_cast<float2*>(&Out[(size_t)row0 * D_ + col]) =
            make_float2(O[nt2][0] * inv0, O[nt2][1] * inv0);
        *reinterpret_cast<float2*>(&Out[(size_t)row1 * D_ + col]) =
            make_float2(O[nt2][2] * inv1, O[nt2][3] * inv1);
    }
}

// ----------------------------------------------------------------------------
// Fused residual add + LayerNorm. TWO rows per warp (deeper MLP).
// Block 256 = 8 warps = 16 rows; grid = ROWS/16.
// ----------------------------------------------------------------------------
__global__ __launch_bounds__(256, 6)
void add_ln_kernel(const float* __restrict__ x,
                   const float* __restrict__ delta,
                   const float* __restrict__ g,
                   const float* __restrict__ be,
                   float* __restrict__ out)
{
    const int warp = threadIdx.x >> 5;
    const int lane = threadIdx.x & 31;
    const int rowA = blockIdx.x * 16 + warp * 2;
    const int rowB = rowA + 1;
    const int col0 = lane * 8;

    const float4* xa = reinterpret_cast<const float4*>(&x[(size_t)rowA * D_ + col0]);
    const float4* da = reinterpret_cast<const float4*>(&delta[(size_t)rowA * D_ + col0]);
    const float4* xb = reinterpret_cast<const float4*>(&x[(size_t)rowB * D_ + col0]);
    const float4* db = reinterpret_cast<const float4*>(&delta[(size_t)rowB * D_ + col0]);

    float4 xa0 = xa[0], xa1 = xa[1], xb0 = xb[0], xb1 = xb[1];
    float4 da0 = da[0], da1 = da[1], db0 = db[0], db1 = db[1];

    float ra[8], rb[8];
    ra[0] = xa0.x + da0.x; ra[1] = xa0.y + da0.y; ra[2] = xa0.z + da0.z; ra[3] = xa0.w + da0.w;
    ra[4] = xa1.x + da1.x; ra[5] = xa1.y + da1.y; ra[6] = xa1.z + da1.z; ra[7] = xa1.w + da1.w;
    rb[0] = xb0.x + db0.x; rb[1] = xb0.y + db0.y; rb[2] = xb0.z + db0.z; rb[3] = xb0.w + db0.w;
    rb[4] = xb1.x + db1.x; rb[5] = xb1.y + db1.y; rb[6] = xb1.z + db1.z; rb[7] = xb1.w + db1.w;

    float sa = 0.0f, sb = 0.0f;
#pragma unroll
    for (int j = 0; j < 8; j++) { sa += ra[j]; sb += rb[j]; }
#pragma unroll
    for (int off = 16; off > 0; off >>= 1) {
        sa += __shfl_xor_sync(0xffffffffu, sa, off);
        sb += __shfl_xor_sync(0xffffffffu, sb, off);
    }
    const float meanA = sa * (1.0f / 256.0f);
    const float meanB = sb * (1.0f / 256.0f);

    float va = 0.0f, vb = 0.0f;
#pragma unroll
    for (int j = 0; j < 8; j++) {
        float ta = ra[j] - meanA; va = fmaf(ta, ta, va);
        float tb = rb[j] - meanB; vb = fmaf(tb, tb, vb);
    }
#pragma unroll
    for (int off = 16; off > 0; off >>= 1) {
        va += __shfl_xor_sync(0xffffffffu, va, off);
        vb += __shfl_xor_sync(0xffffffffu, vb, off);
    }
    const float rsA = rsqrtf(va * (1.0f / 256.0f) + 1e-5f);
    const float rsB = rsqrtf(vb * (1.0f / 256.0f) + 1e-5f);

    const float4* gg = reinterpret_cast<const float4*>(&g[col0]);
    const float4* bb = reinterpret_cast<const float4*>(&be[col0]);
    float4 g0 = gg[0], g1 = gg[1], e0 = bb[0], e1 = bb[1];
    const float gv[8] = {g0.x, g0.y, g0.z, g0.w, g1.x, g1.y, g1.z, g1.w};
    const float ev[8] = {e0.x, e0.y, e0.z, e0.w, e1.x, e1.y, e1.z, e1.w};

    float oa[8], ob[8];
#pragma unroll
    for (int j = 0; j < 8; j++) {
        oa[j] = (ra[j] - meanA) * rsA * gv[j] + ev[j];
        ob[j] = (rb[j] - meanB) * rsB * gv[j] + ev[j];
    }

    float4* outA = reinterpret_cast<float4*>(&out[(size_t)rowA * D_ + col0]);
    float4* outB = reinterpret_cast<float4*>(&out[(size_t)rowB * D_ + col0]);
    outA[0] = make_float4(oa[0], oa[1], oa[2], oa[3]);
    outA[1] = make_float4(oa[4], oa[5], oa[6], oa[7]);
    outB[0] = make_float4(ob[0], ob[1], ob[2], ob[3]);
    outB[1] = make_float4(ob[4], ob[5], ob[6], ob[7]);
}

// ----------------------------------------------------------------------------
// Host driver
// ----------------------------------------------------------------------------
extern "C" void kernel_launch(void* const* d_in, const int* in_sizes, int n_in,
                              void* d_out, int out_size)
{
    const float* x      = (const float*)d_in[0];
    const float* coords = (const float*)d_in[1];
    const float* Wq     = (const float*)d_in[2];
    const float* bq     = (const float*)d_in[3];
    const float* Wk     = (const float*)d_in[4];
    const float* bk     = (const float*)d_in[5];
    const float* Wv     = (const float*)d_in[6];
    const float* bv     = (const float*)d_in[7];
    const float* alpha  = (const float*)d_in[8];
    const float* W1     = (const float*)d_in[9];
    const float* b1     = (const float*)d_in[10];
    const float* W2     = (const float*)d_in[11];
    const float* b2     = (const float*)d_in[12];
    const float* g1     = (const float*)d_in[13];
    const float* be1    = (const float*)d_in[14];
    const float* g2     = (const float*)d_in[15];
    const float* be2    = (const float*)d_in[16];
    float* out = (float*)d_out;

    float *Qp, *Ap, *Xp, *Hp, *Fp, *KAp, *VAp;
    cudaGetSymbolAddress((void**)&Qp,  g_Q);
    cudaGetSymbolAddress((void**)&Ap,  g_ATT);
    cudaGetSymbolAddress((void**)&Xp,  g_X);
    cudaGetSymbolAddress((void**)&Hp,  g_Hb);
    cudaGetSymbolAddress((void**)&Fp,  g_Fb);
    cudaGetSymbolAddress((void**)&KAp, g_Kaug);
    cudaGetSymbolAddress((void**)&VAp, g_Vaug);

    cudaFuncSetAttribute(qkv_kernel,
                         cudaFuncAttributeMaxDynamicSharedMemorySize, GEMM_SMEM);
    cudaFuncSetAttribute(ff_kernel<true>,
                         cudaFuncAttributeMaxDynamicSharedMemorySize, GEMM_SMEM);
    cudaFuncSetAttribute(ff_kernel<false>,
                         cudaFuncAttributeMaxDynamicSharedMemorySize, GEMM_SMEM);
    cudaFuncSetAttribute(attn_mma_kernel,
                         cudaFuncAttributeMaxDynamicSharedMemorySize, ATTN_SMEM);

    const dim3 gQKV(D_ / 128, ROWS / 128, 3);
    const dim3 gFF1(FF_ / 128, ROWS / 128);
    const dim3 gFF2(D_ / 128, ROWS / 128);
    const dim3 gAttn(B_ * H_, N_ / 128);

    // layer-invariant coords rows of Kaug: fill once per launch
    fill_kcoords_kernel<<<512, 256>>>(coords, KAp);

    const float* cur = x;
    for (int i = 0; i < L_; i++) {
        qkv_kernel<<<gQKV, 256, GEMM_SMEM>>>(
            cur,
            Wq + (size_t)i * D_ * D_, Wk + (size_t)i * D_ * D_, Wv + (size_t)i * D_ * D_,
            bq + i * D_, bk + i * D_, bv + i * D_,
            Qp, KAp, VAp);

        attn_mma_kernel<<<gAttn, 256, ATTN_SMEM>>>(Qp, KAp, VAp, coords, alpha, i, Ap);

        add_ln_kernel<<<ROWS / 16, 256>>>(cur, Ap, g1 + i * D_, be1 + i * D_, Xp);

        ff_kernel<true ><<<gFF1, 256, GEMM_SMEM>>>(Xp, W1 + (size_t)i * D_ * FF_,
                                                   b1 + i * FF_, Hp, FF_, D_);
        ff_kernel<false><<<gFF2, 256, GEMM_SMEM>>>(Hp, W2 + (size_t)i * FF_ * D_,
                                                   b2 + i * D_, Fp, D_, FF_);

        float* xo = (i == L_ - 1) ? out : Xp;
        add_ln_kernel<<<ROWS / 16, 256>>>(Xp, Fp, g2 + i * D_, be2 + i * D_, xo);

        cur = Xp;
    }
}

// round 10
// speedup vs baseline: 5.1182x; 1.0230x over previous
#include <cuda_runtime.h>
#include <cstdint>

// ----------------------------------------------------------------------------
// Problem constants
// ----------------------------------------------------------------------------
constexpr int B_  = 8;
constexpr int N_  = 1024;
constexpr int D_  = 256;
constexpr int H_  = 8;
constexpr int DK_ = 32;
constexpr int FF_ = 1024;
constexpr int L_  = 4;
constexpr int ROWS = B_ * N_;          // 8192 token rows

// ----------------------------------------------------------------------------
// Scratch (device globals: no allocation allowed)
// ----------------------------------------------------------------------------
__device__ float g_Q  [ROWS * D_];
__device__ float g_ATT[ROWS * D_];
__device__ float g_X  [ROWS * D_];
__device__ float g_Hb [ROWS * FF_];
// Attention staging buffers in mma-fragment-tiled layout.
// K' : per (bh, ktile): 40 kk x 128 keys -> 5120 floats (kk>=32 = coords rows)
// V  : per (bh, ktile): 128 keys x 32 dk -> 4096 floats
__device__ __align__(16) float g_Kaug[64 * 8 * 5120];
__device__ __align__(16) float g_Vaug[64 * 8 * 4096];

// ----------------------------------------------------------------------------
// Helpers
// ----------------------------------------------------------------------------
__device__ __forceinline__ uint32_t smem_u32(const void* p) {
    return (uint32_t)__cvta_generic_to_shared(p);
}
__device__ __forceinline__ void cp16(uint32_t s, const void* g) {
    asm volatile("cp.async.cg.shared.global [%0], [%1], 16;" :: "r"(s), "l"(g));
}
__device__ __forceinline__ void cp_commit() {
    asm volatile("cp.async.commit_group;" ::: "memory");
}
template <int NN>
__device__ __forceinline__ void cp_wait() {
    asm volatile("cp.async.wait_group %0;" :: "n"(NN) : "memory");
}
__device__ __forceinline__ void mma_tf32(float* c, const uint32_t* a, const uint32_t* b) {
    asm volatile(
        "mma.sync.aligned.m16n8k8.row.col.f32.tf32.tf32.f32 "
        "{%0,%1,%2,%3},{%4,%5,%6,%7},{%8,%9},{%0,%1,%2,%3};"
        : "+f"(c[0]), "+f"(c[1]), "+f"(c[2]), "+f"(c[3])
        : "r"(a[0]), "r"(a[1]), "r"(a[2]), "r"(a[3]), "r"(b[0]), "r"(b[1]));
}

// ----------------------------------------------------------------------------
// tf32 MMA GEMM core (128x128 tile): 3-stage cp.async pipeline.
// ----------------------------------------------------------------------------
constexpr int A_TILE_U32 = 128 * 32;
constexpr int B_TILE_U32 = 32 * 136;
constexpr int STAGE_U32  = A_TILE_U32 + B_TILE_U32;            // 8448
constexpr int GEMM_SMEM  = 3 * STAGE_U32 * 4;                  // 101376 bytes

__device__ __forceinline__ void gemm_accum(const float* __restrict__ A,
                                           const float* __restrict__ Bw,
                                           int Nn, int Kk,
                                           float acc[2][8][4])
{
    extern __shared__ uint32_t sm[];

    const int tid  = threadIdx.x;
    const int lane = tid & 31;
    const int warp = tid >> 5;
    const int gid  = lane >> 2;
    const int tig  = lane & 3;
    const int wm   = warp & 3;
    const int wn   = warp >> 2;

    const int rowBase = blockIdx.y * 128;
    const int colBase = blockIdx.x * 128;

    int aR[4], aS[4], bR[4], bS[4], aC4[4], bC4[4];
#pragma unroll
    for (int i = 0; i < 4; i++) {
        int idx = tid + i * 256;
        int r  = idx >> 3;
        int c4 = (idx & 7) << 2;
        aR[i] = r; aS[i] = r * 32 + (c4 ^ ((r & 7) << 2)); aC4[i] = c4;
        int rb  = idx >> 5;
        int cb4 = (idx & 31) << 2;
        bR[i] = rb; bS[i] = rb * 136 + cb4; bC4[i] = cb4;
    }

    auto issue = [&](int t, int buf) {
        const int k0 = t * 32;
        uint32_t* As = sm + buf * STAGE_U32;
        uint32_t* Bs = As + A_TILE_U32;
#pragma unroll
        for (int i = 0; i < 4; i++)
            cp16(smem_u32(&As[aS[i]]),
                 &A[(size_t)(rowBase + aR[i]) * Kk + k0 + aC4[i]]);
#pragma unroll
        for (int i = 0; i < 4; i++)
            cp16(smem_u32(&Bs[bS[i]]),
                 &Bw[(size_t)(k0 + bR[i]) * Nn + colBase + bC4[i]]);
        cp_commit();
    };

#pragma unroll
    for (int mt = 0; mt < 2; mt++)
#pragma unroll
        for (int nt = 0; nt < 8; nt++)
#pragma unroll
            for (int j = 0; j < 4; j++) acc[mt][nt][j] = 0.0f;

    const int T = Kk >> 5;
    issue(0, 0);
    issue(1, 1);

    int buf = 0;
    for (int t = 0; t < T; t++) {
        if (t + 1 < T) cp_wait<1>(); else cp_wait<0>();
        __syncthreads();

        const uint32_t* Ab = sm + buf * STAGE_U32;
        const uint32_t* Bb = Ab + A_TILE_U32;

#pragma unroll
        for (int kk = 0; kk < 32; kk += 8) {
            uint32_t a[2][4];
#pragma unroll
            for (int mt = 0; mt < 2; mt++) {
                const int m  = wm * 32 + mt * 16 + gid;
                const int sw = (m & 7) << 2;
                const int b0 = m * 32;
                const int b1 = b0 + 8 * 32;
                a[mt][0] = Ab[b0 + (kk ^ sw) + tig];
                a[mt][1] = Ab[b1 + (kk ^ sw) + tig];
                a[mt][2] = Ab[b0 + ((kk + 4) ^ sw) + tig];
                a[mt][3] = Ab[b1 + ((kk + 4) ^ sw) + tig];
            }
            uint32_t b[8][2];
#pragma unroll
            for (int nt = 0; nt < 8; nt++) {
                const int n = wn * 64 + nt * 8 + gid;
                b[nt][0] = Bb[(kk + tig) * 136 + n];
                b[nt][1] = Bb[(kk + tig + 4) * 136 + n];
            }
#pragma unroll
            for (int mt = 0; mt < 2; mt++)
#pragma unroll
                for (int nt = 0; nt < 8; nt++)
                    mma_tf32(acc[mt][nt], a[mt], b[nt]);
        }

        if (t + 2 < T) {
            int nbuf = buf + 2; if (nbuf >= 3) nbuf -= 3;
            issue(t + 2, nbuf);
        }
        if (++buf == 3) buf = 0;
    }
}

// ----------------------------------------------------------------------------
// QKV kernel. z=0: Q plain. z=1: K -> Kaug fragment-tiled. z=2: V -> Vaug.
// ----------------------------------------------------------------------------
__global__ __launch_bounds__(256, 2)
void qkv_kernel(const float* __restrict__ A,
                const float* __restrict__ Wq, const float* __restrict__ Wk,
                const float* __restrict__ Wv,
                const float* __restrict__ bq, const float* __restrict__ bk,
                const float* __restrict__ bv,
                float* __restrict__ Qo, float* __restrict__ Kaug,
                float* __restrict__ Vaug)
{
    const float* Bw; const float* bias;
    if (blockIdx.z == 0)      { Bw = Wq; bias = bq; }
    else if (blockIdx.z == 1) { Bw = Wk; bias = bk; }
    else                      { Bw = Wv; bias = bv; }

    float acc[2][8][4];
    gemm_accum(A, Bw, D_, D_, acc);

    const int lane = threadIdx.x & 31;
    const int warp = threadIdx.x >> 5;
    const int gid  = lane >> 2;
    const int tig  = lane & 3;
    const int wm   = warp & 3;
    const int wn   = warp >> 2;
    const int rowBase = blockIdx.y * 128;
    const int colBase = blockIdx.x * 128;

    if (blockIdx.z == 0) {
#pragma unroll
        for (int mt = 0; mt < 2; mt++) {
            const int row0 = rowBase + wm * 32 + mt * 16 + gid;
            const int row1 = row0 + 8;
#pragma unroll
            for (int nt = 0; nt < 8; nt++) {
                const int col = colBase + wn * 64 + nt * 8 + 2 * tig;
                float2 bb = *reinterpret_cast<const float2*>(&bias[col]);
                *reinterpret_cast<float2*>(&Qo[(size_t)row0 * D_ + col]) =
                    make_float2(acc[mt][nt][0] + bb.x, acc[mt][nt][1] + bb.y);
                *reinterpret_cast<float2*>(&Qo[(size_t)row1 * D_ + col]) =
                    make_float2(acc[mt][nt][2] + bb.x, acc[mt][nt][3] + bb.y);
            }
        }
    } else if (blockIdx.z == 1) {
#pragma unroll
        for (int mt = 0; mt < 2; mt++) {
            const int row0 = rowBase + wm * 32 + mt * 16 + gid;
            const int b    = row0 >> 10;
            const int n0   = row0 & 1023;
            const int kt   = n0 >> 7;
            const int key0 = n0 & 127;
            const int key1 = key0 + 8;
#pragma unroll
            for (int nt = 0; nt < 8; nt++) {
                const int col = colBase + wn * 64 + nt * 8 + 2 * tig;
                const int h   = col >> 5;
                const int kk0 = col & 31;
                float2 bb = *reinterpret_cast<const float2*>(&bias[col]);
                const size_t base = (size_t)((b * 8 + h) * 8 + kt) * 5120;
#pragma unroll
                for (int e = 0; e < 4; e++) {
                    const int kk  = kk0 + (e & 1);
                    const int key = (e < 2) ? key0 : key1;
                    const float v = acc[mt][nt][e] + ((e & 1) ? bb.y : bb.x);
                    Kaug[base + (size_t)(((kk >> 2) * 16 + (key >> 3)) * 32
                                         + (kk & 3) * 8 + (key & 7))] = v;
                }
            }
        }
    } else {
#pragma unroll
        for (int mt = 0; mt < 2; mt++) {
            const int row0 = rowBase + wm * 32 + mt * 16 + gid;
            const int b    = row0 >> 10;
            const int n0   = row0 & 1023;
            const int kt   = n0 >> 7;
            const int key0 = n0 & 127;
            const int key1 = key0 + 8;
#pragma unroll
            for (int nt = 0; nt < 8; nt++) {
                const int col = colBase + wn * 64 + nt * 8 + 2 * tig;
                const int h   = col >> 5;
                const int dk0 = col & 31;
                float2 bb = *reinterpret_cast<const float2*>(&bias[col]);
                const size_t base = (size_t)((b * 8 + h) * 8 + kt) * 4096;
#pragma unroll
                for (int e = 0; e < 4; e++) {
                    const int dk  = dk0 + (e & 1);
                    const int key = (e < 2) ? key0 : key1;
                    const float v = acc[mt][nt][e] + ((e & 1) ? bb.y : bb.x);
                    Vaug[base + (size_t)(((key >> 2) * 4 + (dk >> 3)) * 32
                                         + (key & 3) * 8 + (dk & 7))] = v;
                }
            }
        }
    }
}

// ff1: plain 128x128-tile GEMM with ReLU.
__global__ __launch_bounds__(256, 2)
void ff1_kernel(const float* __restrict__ A, const float* __restrict__ Bw,
                const float* __restrict__ bias, float* __restrict__ C)
{
    float acc[2][8][4];
    gemm_accum(A, Bw, FF_, D_, acc);

    const int lane = threadIdx.x & 31;
    const int warp = threadIdx.x >> 5;
    const int gid  = lane >> 2;
    const int tig  = lane & 3;
    const int wm   = warp & 3;
    const int wn   = warp >> 2;
    const int rowBase = blockIdx.y * 128;
    const int colBase = blockIdx.x * 128;

#pragma unroll
    for (int mt = 0; mt < 2; mt++) {
        const int row0 = rowBase + wm * 32 + mt * 16 + gid;
        const int row1 = row0 + 8;
#pragma unroll
        for (int nt = 0; nt < 8; nt++) {
            const int col = colBase + wn * 64 + nt * 8 + 2 * tig;
            float2 bb = *reinterpret_cast<const float2*>(&bias[col]);
            float v0 = fmaxf(acc[mt][nt][0] + bb.x, 0.0f);
            float v1 = fmaxf(acc[mt][nt][1] + bb.y, 0.0f);
            float v2 = fmaxf(acc[mt][nt][2] + bb.x, 0.0f);
            float v3 = fmaxf(acc[mt][nt][3] + bb.y, 0.0f);
            *reinterpret_cast<float2*>(&C[(size_t)row0 * FF_ + col]) = make_float2(v0, v1);
            *reinterpret_cast<float2*>(&C[(size_t)row1 * FF_ + col]) = make_float2(v2, v3);
        }
    }
}

// ----------------------------------------------------------------------------
// Fused ff2 + residual + LayerNorm.
// CTA tile: 64 rows x 256 cols (FULL model row per CTA), K = 1024, grid 128.
// 8 warps: wm = warp&1 (2 x 32 rows), wn = warp>>1 (4 x 64 cols).
// Epilogue: v = acc + bias + X; row mean/var via quad shuffle + smem; LN; store.
// ----------------------------------------------------------------------------
constexpr int A2_TILE_U32 = 64 * 32;                            // 2048
constexpr int B2_TILE_U32 = 32 * 264;                           // 8448
constexpr int STAGE2_U32  = A2_TILE_U32 + B2_TILE_U32;          // 10496
constexpr int FF2_SMEM    = 3 * STAGE2_U32 * 4;                 // 125952 bytes

__global__ __launch_bounds__(256, 1)
void ff2_ln_kernel(const float* __restrict__ Hb,
                   const float* __restrict__ W2,
                   const float* __restrict__ b2,
                   const float* __restrict__ X,
                   const float* __restrict__ g,
                   const float* __restrict__ be,
                   float* __restrict__ out)
{
    extern __shared__ uint32_t sm[];

    const int tid  = threadIdx.x;
    const int lane = tid & 31;
    const int warp = tid >> 5;
    const int gid  = lane >> 2;
    const int tig  = lane & 3;
    const int wm   = warp & 1;
    const int wn   = warp >> 1;

    const int rowBase = blockIdx.x * 64;

    // staging: A = 2 float4/thread, B = 8 float4/thread
    int aR[2], aS[2], aC4[2];
#pragma unroll
    for (int i = 0; i < 2; i++) {
        int idx = tid + i * 256;
        int r  = idx >> 3;
        int c4 = (idx & 7) << 2;
        aR[i] = r; aS[i] = r * 32 + (c4 ^ ((r & 7) << 2)); aC4[i] = c4;
    }
    int bR[8], bS[8], bC4[8];
#pragma unroll
    for (int i = 0; i < 8; i++) {
        int idx = tid + i * 256;
        int rb  = idx >> 6;            // 0..31
        int cb4 = (idx & 63) << 2;     // 0..252
        bR[i] = rb; bS[i] = rb * 264 + cb4; bC4[i] = cb4;
    }

    auto issue = [&](int t, int buf) {
        const int k0 = t * 32;
        uint32_t* As = sm + buf * STAGE2_U32;
        uint32_t* Bs = As + A2_TILE_U32;
#pragma unroll
        for (int i = 0; i < 2; i++)
            cp16(smem_u32(&As[aS[i]]),
                 &Hb[(size_t)(rowBase + aR[i]) * FF_ + k0 + aC4[i]]);
#pragma unroll
        for (int i = 0; i < 8; i++)
            cp16(smem_u32(&Bs[bS[i]]),
                 &W2[(size_t)(k0 + bR[i]) * D_ + bC4[i]]);
        cp_commit();
    };

    float acc[2][8][4];
#pragma unroll
    for (int mt = 0; mt < 2; mt++)
#pragma unroll
        for (int nt = 0; nt < 8; nt++)
#pragma unroll
            for (int j = 0; j < 4; j++) acc[mt][nt][j] = 0.0f;

    const int T = FF_ >> 5;            // 32
    issue(0, 0);
    issue(1, 1);

    int buf = 0;
    for (int t = 0; t < T; t++) {
        if (t + 1 < T) cp_wait<1>(); else cp_wait<0>();
        __syncthreads();

        const uint32_t* Ab = sm + buf * STAGE2_U32;
        const uint32_t* Bb = Ab + A2_TILE_U32;

#pragma unroll
        for (int kk = 0; kk < 32; kk += 8) {
            uint32_t a[2][4];
#pragma unroll
            for (int mt = 0; mt < 2; mt++) {
                const int m  = wm * 32 + mt * 16 + gid;
                const int sw = (m & 7) << 2;
                const int b0 = m * 32;
                const int b1 = b0 + 8 * 32;
                a[mt][0] = Ab[b0 + (kk ^ sw) + tig];
                a[mt][1] = Ab[b1 + (kk ^ sw) + tig];
                a[mt][2] = Ab[b0 + ((kk + 4) ^ sw) + tig];
                a[mt][3] = Ab[b1 + ((kk + 4) ^ sw) + tig];
            }
            uint32_t b[8][2];
#pragma unroll
            for (int nt = 0; nt < 8; nt++) {
                const int n = wn * 64 + nt * 8 + gid;
                b[nt][0] = Bb[(kk + tig) * 264 + n];
                b[nt][1] = Bb[(kk + tig + 4) * 264 + n];
            }
#pragma unroll
            for (int mt = 0; mt < 2; mt++)
#pragma unroll
                for (int nt = 0; nt < 8; nt++)
                    mma_tf32(acc[mt][nt], a[mt], b[nt]);
        }

        if (t + 2 < T) {
            int nbuf = buf + 2; if (nbuf >= 3) nbuf -= 3;
            issue(t + 2, nbuf);
        }
        if (++buf == 3) buf = 0;
    }

    // ---- epilogue: bias + residual, per-row mean/var, LN ----
    __syncthreads();                       // smem free for reduction scratch
    float* red = reinterpret_cast<float*>(sm);   // [64 rows][8] = sum/sq per wn

#pragma unroll
    for (int mt = 0; mt < 2; mt++) {
        const int rloc0 = wm * 32 + mt * 16 + gid;
        const int rloc1 = rloc0 + 8;
        float s0 = 0.0f, q0 = 0.0f, s1 = 0.0f, q1 = 0.0f;
#pragma unroll
        for (int nt = 0; nt < 8; nt++) {
            const int col = wn * 64 + nt * 8 + 2 * tig;
            float2 bb = *reinterpret_cast<const float2*>(&b2[col]);
            float2 x0 = *reinterpret_cast<const float2*>(
                &X[(size_t)(rowBase + rloc0) * D_ + col]);
            float2 x1 = *reinterpret_cast<const float2*>(
                &X[(size_t)(rowBase + rloc1) * D_ + col]);
            float v0 = acc[mt][nt][0] + bb.x + x0.x;
            float v1 = acc[mt][nt][1] + bb.y + x0.y;
            float v2 = acc[mt][nt][2] + bb.x + x1.x;
            float v3 = acc[mt][nt][3] + bb.y + x1.y;
            acc[mt][nt][0] = v0; acc[mt][nt][1] = v1;
            acc[mt][nt][2] = v2; acc[mt][nt][3] = v3;
            s0 += v0 + v1; q0 = fmaf(v0, v0, fmaf(v1, v1, q0));
            s1 += v2 + v3; q1 = fmaf(v2, v2, fmaf(v3, v3, q1));
        }
        // reduce over the 4 tig lanes of this row
        s0 += __shfl_xor_sync(0xffffffffu, s0, 1);
        s0 += __shfl_xor_sync(0xffffffffu, s0, 2);
        q0 += __shfl_xor_sync(0xffffffffu, q0, 1);
        q0 += __shfl_xor_sync(0xffffffffu, q0, 2);
        s1 += __shfl_xor_sync(0xffffffffu, s1, 1);
        s1 += __shfl_xor_sync(0xffffffffu, s1, 2);
        q1 += __shfl_xor_sync(0xffffffffu, q1, 1);
        q1 += __shfl_xor_sync(0xffffffffu, q1, 2);
        if (tig == 0) {
            red[rloc0 * 8 + wn * 2 + 0] = s0;
            red[rloc0 * 8 + wn * 2 + 1] = q0;
            red[rloc1 * 8 + wn * 2 + 0] = s1;
            red[rloc1 * 8 + wn * 2 + 1] = q1;
        }
    }
    __syncthreads();

#pragma unroll
    for (int mt = 0; mt < 2; mt++) {
#pragma unroll
        for (int rr = 0; rr < 2; rr++) {
            const int rloc = wm * 32 + mt * 16 + gid + rr * 8;
            const float* rp = &red[rloc * 8];
            const float sum = rp[0] + rp[2] + rp[4] + rp[6];
            const float sq  = rp[1] + rp[3] + rp[5] + rp[7];
            const float mean = sum * (1.0f / 256.0f);
            const float var  = sq * (1.0f / 256.0f) - mean * mean;
            const float rs   = rsqrtf(var + 1e-5f);
            const int row = rowBase + rloc;
#pragma unroll
            for (int nt = 0; nt < 8; nt++) {
                const int col = wn * 64 + nt * 8 + 2 * tig;
                float2 gv = *reinterpret_cast<const float2*>(&g[col]);
                float2 ev = *reinterpret_cast<const float2*>(&be[col]);
                const float a0 = acc[mt][nt][rr * 2 + 0];
                const float a1 = acc[mt][nt][rr * 2 + 1];
                *reinterpret_cast<float2*>(&out[(size_t)row * D_ + col]) =
                    make_float2((a0 - mean) * rs * gv.x + ev.x,
                                (a1 - mean) * rs * gv.y + ev.y);
            }
        }
    }
}

// ----------------------------------------------------------------------------
// One-time fill of Kaug coords rows (kk 32..39): layer-invariant.
// ----------------------------------------------------------------------------
__global__ __launch_bounds__(256)
void fill_kcoords_kernel(const float* __restrict__ coords,
                         float* __restrict__ Kaug)
{
    const int t  = blockIdx.x;
    const int kt = t & 7;
    const int b  = (t >> 3) >> 3;
    const size_t base = (size_t)t * 5120 + 128 * 32;
#pragma unroll
    for (int j = 0; j < 4; j++) {
        const int e   = threadIdx.x + j * 256;
        const int rel = e >> 5;
        const int ln  = e & 31;
        const int kk  = 32 + (rel >> 4) * 4 + (ln >> 3);
        const int key = (rel & 15) * 8 + (ln & 7);
        float v = 0.0f;
        if (kk < 35)
            v = coords[(size_t)(b * N_ + kt * 128 + key) * 3 + (kk - 32)];
        Kaug[base + e] = v;
    }
}

// ----------------------------------------------------------------------------
// tf32 MMA flash attention. Now 2 CTAs/SM.
// ----------------------------------------------------------------------------
constexpr int KT_FLOATS   = 5120;
constexpr int VT_FLOATS   = 4096;
constexpr int TILE_FLOATS = KT_FLOATS + VT_FLOATS;
constexpr int ATTN_SMEM   = 2 * TILE_FLOATS * 4;

__global__ __launch_bounds__(256, 2)
void attn_mma_kernel(const float* __restrict__ Q,
                     const float* __restrict__ Kaug,
                     const float* __restrict__ Vaug,
                     const float* __restrict__ coords,
                     const float* __restrict__ alpha,
                     int layer,
                     float* __restrict__ Out)
{
    extern __shared__ float smf[];

    const int tid  = threadIdx.x;
    const int lane = tid & 31;
    const int w    = tid >> 5;
    const int gid  = lane >> 2;
    const int tig  = lane & 3;

    const int bh = blockIdx.x;
    const int b  = bh >> 3;
    const int h  = bh & 7;
    const int q0 = blockIdx.y * 128;

    const float scale  = 0.17677669529663687f;
    const float alphav = alpha[layer];

    uint32_t qf[5][4];
    {
        const int row0 = b * N_ + q0 + w * 16 + gid;
#pragma unroll
        for (int ks = 0; ks < 5; ks++) {
#pragma unroll
            for (int r = 0; r < 4; r++) {
                const int row = row0 + (r & 1) * 8;
                const int kk  = ks * 8 + tig + ((r >> 1) << 2);
                float v;
                if (kk < 32)      v = Q[(size_t)row * D_ + h * DK_ + kk] * scale;
                else if (kk < 35) v = alphav * coords[(size_t)row * 3 + (kk - 32)];
                else              v = 0.0f;
                qf[ks][r] = __float_as_uint(v);
            }
        }
    }

    auto issue = [&](int t, int buf) {
        const float* srcK = Kaug + (size_t)(bh * 8 + t) * KT_FLOATS;
        float* dstK = smf + buf * TILE_FLOATS;
#pragma unroll
        for (int j = 0; j < 5; j++) {
            const int i16 = tid + j * 256;
            cp16(smem_u32(dstK + i16 * 4), srcK + i16 * 4);
        }
        const float* srcV = Vaug + (size_t)(bh * 8 + t) * VT_FLOATS;
        float* dstV = smf + buf * TILE_FLOATS + KT_FLOATS;
#pragma unroll
        for (int j = 0; j < 4; j++) {
            const int i16 = tid + j * 256;
            cp16(smem_u32(dstV + i16 * 4), srcV + i16 * 4);
        }
        cp_commit();
    };

    float O[4][4];
#pragma unroll
    for (int i = 0; i < 4; i++)
#pragma unroll
        for (int j = 0; j < 4; j++) O[i][j] = 0.0f;
    float m0 = -1e30f, m1 = -1e30f, l0 = 0.0f, l1 = 0.0f;

    const int klane = tig * 8 + gid;
    const int src0  = (gid << 2) + (tig >> 1);
    const int src1  = src0 + 2;

    issue(0, 0);

    for (int t = 0; t < 8; t++) {
        if (t < 7) { issue(t + 1, (t + 1) & 1); cp_wait<1>(); }
        else       { cp_wait<0>(); }
        __syncthreads();

        const uint32_t* Kb = reinterpret_cast<const uint32_t*>(smf + (t & 1) * TILE_FLOATS);
        const uint32_t* Vb = Kb + KT_FLOATS;

        float s[16][4];
#pragma unroll
        for (int nt = 0; nt < 16; nt++)
#pragma unroll
            for (int j = 0; j < 4; j++) s[nt][j] = 0.0f;

#pragma unroll
        for (int ks = 0; ks < 5; ks++) {
#pragma unroll
            for (int nt = 0; nt < 16; nt++) {
                uint32_t bfr[2];
                bfr[0] = Kb[(32 * ks + nt) * 32 + klane];
                bfr[1] = Kb[(32 * ks + 16 + nt) * 32 + klane];
                mma_tf32(s[nt], qf[ks], bfr);
            }
        }

        float mx0 = -1e30f, mx1 = -1e30f;
#pragma unroll
        for (int nt = 0; nt < 16; nt++) {
            mx0 = fmaxf(mx0, fmaxf(s[nt][0], s[nt][1]));
            mx1 = fmaxf(mx1, fmaxf(s[nt][2], s[nt][3]));
        }
        mx0 = fmaxf(mx0, __shfl_xor_sync(0xffffffffu, mx0, 1));
        mx0 = fmaxf(mx0, __shfl_xor_sync(0xffffffffu, mx0, 2));
        mx1 = fmaxf(mx1, __shfl_xor_sync(0xffffffffu, mx1, 1));
        mx1 = fmaxf(mx1, __shfl_xor_sync(0xffffffffu, mx1, 2));

        const float mn0 = fmaxf(m0, mx0);
        const float mn1 = fmaxf(m1, mx1);
        const float c0  = __expf(m0 - mn0);
        const float c1  = __expf(m1 - mn1);
        m0 = mn0; m1 = mn1;

        float rs0 = 0.0f, rs1 = 0.0f;
#pragma unroll
        for (int nt = 0; nt < 16; nt++) {
            s[nt][0] = __expf(s[nt][0] - mn0);
            s[nt][1] = __expf(s[nt][1] - mn0);
            s[nt][2] = __expf(s[nt][2] - mn1);
            s[nt][3] = __expf(s[nt][3] - mn1);
            rs0 += s[nt][0] + s[nt][1];
            rs1 += s[nt][2] + s[nt][3];
        }
        rs0 += __shfl_xor_sync(0xffffffffu, rs0, 1);
        rs0 += __shfl_xor_sync(0xffffffffu, rs0, 2);
        rs1 += __shfl_xor_sync(0xffffffffu, rs1, 1);
        rs1 += __shfl_xor_sync(0xffffffffu, rs1, 2);
        l0 = l0 * c0 + rs0;
        l1 = l1 * c1 + rs1;

#pragma unroll
        for (int nt2 = 0; nt2 < 4; nt2++) {
            O[nt2][0] *= c0; O[nt2][1] *= c0;
            O[nt2][2] *= c1; O[nt2][3] *= c1;
        }

#pragma unroll
        for (int ks = 0; ks < 16; ks++) {
            uint32_t a[4];
            {
                float v0 = __shfl_sync(0xffffffffu, s[ks][0], src0);
                float v1 = __shfl_sync(0xffffffffu, s[ks][1], src0);
                float v2 = __shfl_sync(0xffffffffu, s[ks][2], src0);
                float v3 = __shfl_sync(0xffffffffu, s[ks][3], src0);
                float u0 = __shfl_sync(0xffffffffu, s[ks][0], src1);
                float u1 = __shfl_sync(0xffffffffu, s[ks][1], src1);
                float u2 = __shfl_sync(0xffffffffu, s[ks][2], src1);
                float u3 = __shfl_sync(0xffffffffu, s[ks][3], src1);
                const bool odd = (tig & 1);
                a[0] = __float_as_uint(odd ? v1 : v0);
                a[1] = __float_as_uint(odd ? v3 : v2);
                a[2] = __float_as_uint(odd ? u1 : u0);
                a[3] = __float_as_uint(odd ? u3 : u2);
            }
#pragma unroll
            for (int nt2 = 0; nt2 < 4; nt2++) {
                uint32_t bfr[2];
                bfr[0] = Vb[(8 * ks + nt2) * 32 + klane];
                bfr[1] = Vb[(8 * ks + 4 + nt2) * 32 + klane];
                mma_tf32(O[nt2], a, bfr);
            }
        }
        __syncthreads();
    }

    const float inv0 = 1.0f / l0;
    const float inv1 = 1.0f / l1;
    const int row0 = b * N_ + q0 + w * 16 + gid;
    const int row1 = row0 + 8;
#pragma unroll
    for (int nt2 = 0; nt2 < 4; nt2++) {
        const int col = h * DK_ + nt2 * 8 + 2 * tig;
        *reinterpret_cast<float2*>(&Out[(size_t)row0 * D_ + col]) =
            make_float2(O[nt2][0] * inv0, O[nt2][1] * inv0);
        *reinterpret_cast<float2*>(&Out[(size_t)row1 * D_ + col]) =
            make_float2(O[nt2][2] * inv1, O[nt2][3] * inv1);
    }
}

// ----------------------------------------------------------------------------
// Fused residual add + LayerNorm (for LN1 only). Two rows per warp.
// ----------------------------------------------------------------------------
__global__ __launch_bounds__(256, 6)
void add_ln_kernel(const float* __restrict__ x,
                   const float* __restrict__ delta,
                   const float* __restrict__ g,
                   const float* __restrict__ be,
                   float* __restrict__ out)
{
    const int warp = threadIdx.x >> 5;
    const int lane = threadIdx.x & 31;
    const int rowA = blockIdx.x * 16 + warp * 2;
    const int rowB = rowA + 1;
    const int col0 = lane * 8;

    const float4* xa = reinterpret_cast<const float4*>(&x[(size_t)rowA * D_ + col0]);
    const float4* da = reinterpret_cast<const float4*>(&delta[(size_t)rowA * D_ + col0]);
    const float4* xb = reinterpret_cast<const float4*>(&x[(size_t)rowB * D_ + col0]);
    const float4* db = reinterpret_cast<const float4*>(&delta[(size_t)rowB * D_ + col0]);

    float4 xa0 = xa[0], xa1 = xa[1], xb0 = xb[0], xb1 = xb[1];
    float4 da0 = da[0], da1 = da[1], db0 = db[0], db1 = db[1];

    float ra[8], rb[8];
    ra[0] = xa0.x + da0.x; ra[1] = xa0.y + da0.y; ra[2] = xa0.z + da0.z; ra[3] = xa0.w + da0.w;
    ra[4] = xa1.x + da1.x; ra[5] = xa1.y + da1.y; ra[6] = xa1.z + da1.z; ra[7] = xa1.w + da1.w;
    rb[0] = xb0.x + db0.x; rb[1] = xb0.y + db0.y; rb[2] = xb0.z + db0.z; rb[3] = xb0.w + db0.w;
    rb[4] = xb1.x + db1.x; rb[5] = xb1.y + db1.y; rb[6] = xb1.z + db1.z; rb[7] = xb1.w + db1.w;

    float sa = 0.0f, sb = 0.0f;
#pragma unroll
    for (int j = 0; j < 8; j++) { sa += ra[j]; sb += rb[j]; }
#pragma unroll
    for (int off = 16; off > 0; off >>= 1) {
        sa += __shfl_xor_sync(0xffffffffu, sa, off);
        sb += __shfl_xor_sync(0xffffffffu, sb, off);
    }
    const float meanA = sa * (1.0f / 256.0f);
    const float meanB = sb * (1.0f / 256.0f);

    float va = 0.0f, vb = 0.0f;
#pragma unroll
    for (int j = 0; j < 8; j++) {
        float ta = ra[j] - meanA; va = fmaf(ta, ta, va);
        float tb = rb[j] - meanB; vb = fmaf(tb, tb, vb);
    }
#pragma unroll
    for (int off = 16; off > 0; off >>= 1) {
        va += __shfl_xor_sync(0xffffffffu, va, off);
        vb += __shfl_xor_sync(0xffffffffu, vb, off);
    }
    const float rsA = rsqrtf(va * (1.0f / 256.0f) + 1e-5f);
    const float rsB = rsqrtf(vb * (1.0f / 256.0f) + 1e-5f);

    const float4* gg = reinterpret_cast<const float4*>(&g[col0]);
    const float4* bb = reinterpret_cast<const float4*>(&be[col0]);
    float4 g0 = gg[0], g1 = gg[1], e0 = bb[0], e1 = bb[1];
    const float gv[8] = {g0.x, g0.y, g0.z, g0.w, g1.x, g1.y, g1.z, g1.w};
    const float ev[8] = {e0.x, e0.y, e0.z, e0.w, e1.x, e1.y, e1.z, e1.w};

    float oa[8], ob[8];
#pragma unroll
    for (int j = 0; j < 8; j++) {
        oa[j] = (ra[j] - meanA) * rsA * gv[j] + ev[j];
        ob[j] = (rb[j] - meanB) * rsB * gv[j] + ev[j];
    }

    float4* outA = reinterpret_cast<float4*>(&out[(size_t)rowA * D_ + col0]);
    float4* outB = reinterpret_cast<float4*>(&out[(size_t)rowB * D_ + col0]);
    outA[0] = make_float4(oa[0], oa[1], oa[2], oa[3]);
    outA[1] = make_float4(oa[4], oa[5], oa[6], oa[7]);
    outB[0] = make_float4(ob[0], ob[1], ob[2], ob[3]);
    outB[1] = make_float4(ob[4], ob[5], ob[6], ob[7]);
}

// ----------------------------------------------------------------------------
// Host driver
// ----------------------------------------------------------------------------
extern "C" void kernel_launch(void* const* d_in, const int* in_sizes, int n_in,
                              void* d_out, int out_size)
{
    const float* x      = (const float*)d_in[0];
    const float* coords = (const float*)d_in[1];
    const float* Wq     = (const float*)d_in[2];
    const float* bq     = (const float*)d_in[3];
    const float* Wk     = (const float*)d_in[4];
    const float* bk     = (const float*)d_in[5];
    const float* Wv     = (const float*)d_in[6];
    const float* bv     = (const float*)d_in[7];
    const float* alpha  = (const float*)d_in[8];
    const float* W1     = (const float*)d_in[9];
    const float* b1     = (const float*)d_in[10];
    const float* W2     = (const float*)d_in[11];
    const float* b2     = (const float*)d_in[12];
    const float* g1     = (const float*)d_in[13];
    const float* be1    = (const float*)d_in[14];
    const float* g2     = (const float*)d_in[15];
    const float* be2    = (const float*)d_in[16];
    float* out = (float*)d_out;

    float *Qp, *Ap, *Xp, *Hp, *KAp, *VAp;
    cudaGetSymbolAddress((void**)&Qp,  g_Q);
    cudaGetSymbolAddress((void**)&Ap,  g_ATT);
    cudaGetSymbolAddress((void**)&Xp,  g_X);
    cudaGetSymbolAddress((void**)&Hp,  g_Hb);
    cudaGetSymbolAddress((void**)&KAp, g_Kaug);
    cudaGetSymbolAddress((void**)&VAp, g_Vaug);

    cudaFuncSetAttribute(qkv_kernel,
                         cudaFuncAttributeMaxDynamicSharedMemorySize, GEMM_SMEM);
    cudaFuncSetAttribute(ff1_kernel,
                         cudaFuncAttributeMaxDynamicSharedMemorySize, GEMM_SMEM);
    cudaFuncSetAttribute(ff2_ln_kernel,
                         cudaFuncAttributeMaxDynamicSharedMemorySize, FF2_SMEM);
    cudaFuncSetAttribute(attn_mma_kernel,
                         cudaFuncAttributeMaxDynamicSharedMemorySize, ATTN_SMEM);

    const dim3 gQKV(D_ / 128, ROWS / 128, 3);
    const dim3 gFF1(FF_ / 128, ROWS / 128);
    const dim3 gAttn(B_ * H_, N_ / 128);

    fill_kcoords_kernel<<<512, 256>>>(coords, KAp);

    const float* cur = x;
    for (int i = 0; i < L_; i++) {
        qkv_kernel<<<gQKV, 256, GEMM_SMEM>>>(
            cur,
            Wq + (size_t)i * D_ * D_, Wk + (size_t)i * D_ * D_, Wv + (size_t)i * D_ * D_,
            bq + i * D_, bk + i * D_, bv + i * D_,
            Qp, KAp, VAp);

        attn_mma_kernel<<<gAttn, 256, ATTN_SMEM>>>(Qp, KAp, VAp, coords, alpha, i, Ap);

        add_ln_kernel<<<ROWS / 16, 256>>>(cur, Ap, g1 + i * D_, be1 + i * D_, Xp);

        ff1_kernel<<<gFF1, 256, GEMM_SMEM>>>(Xp, W1 + (size_t)i * D_ * FF_,
                                             b1 + i * FF_, Hp);

        float* xo = (i == L_ - 1) ? out : Xp;
        ff2_ln_kernel<<<ROWS / 64, 256, FF2_SMEM>>>(
            Hp, W2 + (size_t)i * FF_ * D_, b2 + i * D_,
            Xp, g2 + i * D_, be2 + i * D_, xo);

        cur = Xp;
    }
}